// round 1
// baseline (speedup 1.0000x reference)
#include <cuda_runtime.h>
#include <math.h>

#define BB 2
#define TT 1024
#define LL 12
#define HH 12
#define CC 768
#define VV 50304
#define HD 64
#define MM (BB*TT)    // 2048 rows
#define C3 (3*CC)     // 2304
#define C4 (4*CC)     // 3072

// ---------------- scratch (static device allocations; no cudaMalloc) ----------
__device__ float g_x  [MM*CC];                  // residual stream
__device__ float g_ln [MM*CC];                  // layernorm output
__device__ float g_qkv[MM*C3];                  // qkv projection
__device__ float g_att[(size_t)BB*HH*TT*TT];    // attention scores (100MB)
__device__ float g_y  [MM*CC];                  // attention output (b,t,C)
__device__ float g_mlp[MM*C4];                  // mlp hidden

// ---------------- embedding ---------------------------------------------------
__global__ void embed_kernel(const int* __restrict__ idx,
                             const float* __restrict__ wte,
                             const float* __restrict__ wpe) {
    int i = blockIdx.x * blockDim.x + threadIdx.x;
    if (i >= MM * CC) return;
    int row = i / CC, c = i - row * CC;
    int t = row & (TT - 1);
    int tok = idx[row];
    g_x[i] = wte[(size_t)tok * CC + c] + wpe[(size_t)t * CC + c];
}

// ---------------- layernorm (one block per row, C=768, 256 thr) ---------------
__global__ __launch_bounds__(256) void ln_kernel(const float* __restrict__ in,
                                                 const float* __restrict__ w,
                                                 const float* __restrict__ b,
                                                 float* __restrict__ out) {
    int row = blockIdx.x;
    const float* x = in + (size_t)row * CC;
    int t = threadIdx.x;
    float v[3];
    float s = 0.f, s2 = 0.f;
#pragma unroll
    for (int i = 0; i < 3; i++) {
        float u = x[t + i * 256];
        v[i] = u; s += u; s2 += u * u;
    }
    __shared__ float sh[16];
#pragma unroll
    for (int o = 16; o > 0; o >>= 1) {
        s  += __shfl_down_sync(0xffffffffu, s,  o);
        s2 += __shfl_down_sync(0xffffffffu, s2, o);
    }
    int lane = t & 31, wid = t >> 5;
    if (lane == 0) { sh[wid] = s; sh[8 + wid] = s2; }
    __syncthreads();
    if (wid == 0) {
        s  = (lane < 8) ? sh[lane]     : 0.f;
        s2 = (lane < 8) ? sh[8 + lane] : 0.f;
#pragma unroll
        for (int o = 4; o > 0; o >>= 1) {
            s  += __shfl_down_sync(0xffffffffu, s,  o);
            s2 += __shfl_down_sync(0xffffffffu, s2, o);
        }
        if (lane == 0) { sh[0] = s; sh[8] = s2; }
    }
    __syncthreads();
    float mean = sh[0] * (1.0f / CC);
    float var  = sh[8] * (1.0f / CC) - mean * mean;
    float rstd = rsqrtf(var + 1e-5f);
    float* o = out + (size_t)row * CC;
#pragma unroll
    for (int i = 0; i < 3; i++) {
        int c = t + i * 256;
        o[c] = (v[i] - mean) * rstd * w[c] + b[c];
    }
}

// ---------------- generic NT SGEMM: C[M,N] = A[M,K] * B[N,K]^T (+epilogue) ----
// EPI bits: 1 = +bias[col]   4 = gelu(exact)   2 = +resid[row*N+col]
// Tiles: BM=BN=64, BK=16, 256 threads, 4x4 per thread. All dims divide evenly.
template<int EPI>
__global__ __launch_bounds__(256) void gemm_nt(
    const float* __restrict__ A, const float* __restrict__ Bw,
    const float* __restrict__ bias, const float* __restrict__ resid,
    float* __restrict__ Cm, int N, int K)
{
    __shared__ float As[64][17];
    __shared__ float Bs[64][17];
    int tid = threadIdx.x;
    int tx = tid & 15, ty = tid >> 4;
    const float* Ab = A  + (size_t)(blockIdx.y * 64) * K;
    const float* Bb = Bw + (size_t)(blockIdx.x * 64) * K;
    int lr = tid >> 2;           // 0..63
    int lc = (tid & 3) * 4;      // 0,4,8,12

    float acc[4][4] = {};
    for (int k0 = 0; k0 < K; k0 += 16) {
        float4 a4 = *(const float4*)(Ab + (size_t)lr * K + k0 + lc);
        float4 b4 = *(const float4*)(Bb + (size_t)lr * K + k0 + lc);
        As[lr][lc] = a4.x; As[lr][lc+1] = a4.y; As[lr][lc+2] = a4.z; As[lr][lc+3] = a4.w;
        Bs[lr][lc] = b4.x; Bs[lr][lc+1] = b4.y; Bs[lr][lc+2] = b4.z; Bs[lr][lc+3] = b4.w;
        __syncthreads();
#pragma unroll
        for (int kk = 0; kk < 16; kk++) {
            float af[4], bf[4];
#pragma unroll
            for (int i = 0; i < 4; i++) af[i] = As[ty * 4 + i][kk];
#pragma unroll
            for (int j = 0; j < 4; j++) bf[j] = Bs[tx * 4 + j][kk];
#pragma unroll
            for (int i = 0; i < 4; i++)
#pragma unroll
                for (int j = 0; j < 4; j++)
                    acc[i][j] += af[i] * bf[j];
        }
        __syncthreads();
    }
#pragma unroll
    for (int i = 0; i < 4; i++) {
        int row = blockIdx.y * 64 + ty * 4 + i;
#pragma unroll
        for (int j = 0; j < 4; j++) {
            int col = blockIdx.x * 64 + tx * 4 + j;
            float v = acc[i][j];
            if (EPI & 1) v += bias[col];
            if (EPI & 4) v = 0.5f * v * (1.0f + erff(v * 0.70710678118654752f));
            if (EPI & 2) v += resid[(size_t)row * N + col];
            Cm[(size_t)row * N + col] = v;
        }
    }
}

// ---------------- attention scores: S = scale * Q K^T, causal-masked ----------
// grid: (T/32 k-tiles, T/32 q-tiles, B*H); block 32x32
__global__ __launch_bounds__(1024) void attn_scores(const float* __restrict__ qkv,
                                                    float* __restrict__ att) {
    int kt = blockIdx.x, qt = blockIdx.y, bh = blockIdx.z;
    int b = bh / HH, h = bh - b * HH;
    int tx = threadIdx.x, ty = threadIdx.y;
    int q = qt * 32 + ty, k = kt * 32 + tx;
    float* aout = att + ((size_t)bh * TT + q) * TT + k;
    if (kt > qt) { *aout = -1e30f; return; }   // block fully above diagonal

    __shared__ float qs[32][65];
    __shared__ float ks[32][65];
    const float* base = qkv + ((size_t)b * TT) * C3 + h * HD;
    // each thread loads 2 elements of each 32x64 tile
    qs[ty][tx]      = base[(size_t)(qt * 32 + ty) * C3 + tx];
    qs[ty][tx + 32] = base[(size_t)(qt * 32 + ty) * C3 + tx + 32];
    ks[ty][tx]      = base[(size_t)(kt * 32 + ty) * C3 + CC + tx];
    ks[ty][tx + 32] = base[(size_t)(kt * 32 + ty) * C3 + CC + tx + 32];
    __syncthreads();

    float s = 0.f;
#pragma unroll
    for (int d = 0; d < HD; d++) s += qs[ty][d] * ks[tx][d];
    *aout = (k <= q) ? s * 0.125f : -1e30f;   // 1/sqrt(64) = 0.125
}

// ---------------- row softmax over T=1024 (one block per row) -----------------
__global__ __launch_bounds__(256) void softmax_rows(float* __restrict__ att) {
    float* a = att + (size_t)blockIdx.x * TT;
    int t = threadIdx.x;
    float v[4];
    float mx = -1e30f;
#pragma unroll
    for (int i = 0; i < 4; i++) { v[i] = a[t + i * 256]; mx = fmaxf(mx, v[i]); }
    __shared__ float sh[8];
#pragma unroll
    for (int o = 16; o > 0; o >>= 1) mx = fmaxf(mx, __shfl_xor_sync(0xffffffffu, mx, o));
    int lane = t & 31, wid = t >> 5;
    if (lane == 0) sh[wid] = mx;
    __syncthreads();
    mx = fmaxf(fmaxf(fmaxf(sh[0], sh[1]), fmaxf(sh[2], sh[3])),
               fmaxf(fmaxf(sh[4], sh[5]), fmaxf(sh[6], sh[7])));
    float s = 0.f;
#pragma unroll
    for (int i = 0; i < 4; i++) { v[i] = expf(v[i] - mx); s += v[i]; }
#pragma unroll
    for (int o = 16; o > 0; o >>= 1) s += __shfl_xor_sync(0xffffffffu, s, o);
    __syncthreads();
    if (lane == 0) sh[wid] = s;
    __syncthreads();
    s = sh[0] + sh[1] + sh[2] + sh[3] + sh[4] + sh[5] + sh[6] + sh[7];
    float inv = 1.0f / s;
#pragma unroll
    for (int i = 0; i < 4; i++) a[t + i * 256] = v[i] * inv;
}

// ---------------- AV: Y(b,t,C) += sum_k att[q,k] * V[k,d] ---------------------
// grid: (T/64 q-tiles, B*H); block 256 (16x16, 4x4 per thread), BK=16
__global__ __launch_bounds__(256) void attn_av(const float* __restrict__ att,
                                               const float* __restrict__ qkv,
                                               float* __restrict__ yout) {
    int qt = blockIdx.x, bh = blockIdx.y;
    int b = bh / HH, h = bh - b * HH;
    __shared__ float As[64][17];
    __shared__ float Bs[16][64];
    int tid = threadIdx.x;
    int tx = tid & 15, ty = tid >> 4;
    const float* abase = att + ((size_t)bh * TT + qt * 64) * TT;
    const float* vbase = qkv + ((size_t)b * TT) * C3 + 2 * CC + h * HD;
    int lr = tid >> 2;        // 0..63
    int lc = (tid & 3) * 4;   // 0..12
    int vk = tid >> 6;        // 0..3
    int vd = tid & 63;        // 0..63

    float acc[4][4] = {};
    for (int k0 = 0; k0 < TT; k0 += 16) {
        float4 a4 = *(const float4*)(abase + (size_t)lr * TT + k0 + lc);
        As[lr][lc] = a4.x; As[lr][lc+1] = a4.y; As[lr][lc+2] = a4.z; As[lr][lc+3] = a4.w;
#pragma unroll
        for (int i = 0; i < 4; i++)
            Bs[vk + i * 4][vd] = vbase[(size_t)(k0 + vk + i * 4) * C3 + vd];
        __syncthreads();
#pragma unroll
        for (int kk = 0; kk < 16; kk++) {
            float af[4], bf[4];
#pragma unroll
            for (int i = 0; i < 4; i++) af[i] = As[ty * 4 + i][kk];
#pragma unroll
            for (int j = 0; j < 4; j++) bf[j] = Bs[kk][tx * 4 + j];
#pragma unroll
            for (int i = 0; i < 4; i++)
#pragma unroll
                for (int j = 0; j < 4; j++)
                    acc[i][j] += af[i] * bf[j];
        }
        __syncthreads();
    }
#pragma unroll
    for (int i = 0; i < 4; i++) {
        int t = qt * 64 + ty * 4 + i;
#pragma unroll
        for (int j = 0; j < 4; j++)
            yout[((size_t)b * TT + t) * CC + h * HD + tx * 4 + j] = acc[i][j];
    }
}

// ---------------- host orchestration ------------------------------------------
extern "C" void kernel_launch(void* const* d_in, const int* in_sizes, int n_in,
                              void* d_out, int out_size) {
    (void)in_sizes; (void)n_in; (void)out_size;
    const int*   idx          = (const int*)  d_in[0];
    const float* wte          = (const float*)d_in[1];
    const float* wpe          = (const float*)d_in[2];
    const float* ln1_w        = (const float*)d_in[3];
    const float* ln1_b        = (const float*)d_in[4];
    const float* attn_w       = (const float*)d_in[5];
    const float* attn_b       = (const float*)d_in[6];
    const float* attn_proj_w  = (const float*)d_in[7];
    const float* attn_proj_b  = (const float*)d_in[8];
    const float* ln2_w        = (const float*)d_in[9];
    const float* ln2_b        = (const float*)d_in[10];
    const float* fc_w         = (const float*)d_in[11];
    const float* fc_b         = (const float*)d_in[12];
    const float* mlp_proj_w   = (const float*)d_in[13];
    const float* mlp_proj_b   = (const float*)d_in[14];
    const float* lnf_w        = (const float*)d_in[15];
    const float* lnf_b        = (const float*)d_in[16];
    float* out = (float*)d_out;

    float *x, *ln, *qkv, *att, *y, *mlp;
    cudaGetSymbolAddress((void**)&x,   g_x);
    cudaGetSymbolAddress((void**)&ln,  g_ln);
    cudaGetSymbolAddress((void**)&qkv, g_qkv);
    cudaGetSymbolAddress((void**)&att, g_att);
    cudaGetSymbolAddress((void**)&y,   g_y);
    cudaGetSymbolAddress((void**)&mlp, g_mlp);

    embed_kernel<<<(MM * CC + 255) / 256, 256>>>(idx, wte, wpe);

    for (int l = 0; l < LL; l++) {
        // attn
        ln_kernel<<<MM, 256>>>(x, ln1_w + l * CC, ln1_b + l * CC, ln);
        gemm_nt<1><<<dim3(C3 / 64, MM / 64), 256>>>(
            ln, attn_w + (size_t)l * C3 * CC, attn_b + l * C3, nullptr, qkv, C3, CC);
        attn_scores<<<dim3(TT / 32, TT / 32, BB * HH), dim3(32, 32)>>>(qkv, att);
        softmax_rows<<<BB * HH * TT, 256>>>(att);
        attn_av<<<dim3(TT / 64, BB * HH), 256>>>(att, qkv, y);
        gemm_nt<3><<<dim3(CC / 64, MM / 64), 256>>>(
            y, attn_proj_w + (size_t)l * CC * CC, attn_proj_b + l * CC, x, x, CC, CC);
        // mlp
        ln_kernel<<<MM, 256>>>(x, ln2_w + l * CC, ln2_b + l * CC, ln);
        gemm_nt<5><<<dim3(C4 / 64, MM / 64), 256>>>(
            ln, fc_w + (size_t)l * C4 * CC, fc_b + l * C4, nullptr, mlp, C4, CC);
        gemm_nt<3><<<dim3(CC / 64, MM / 64), 256>>>(
            mlp, mlp_proj_w + (size_t)l * CC * C4, mlp_proj_b + l * CC, x, x, CC, C4);
    }

    ln_kernel<<<MM, 256>>>(x, lnf_w, lnf_b, ln);
    gemm_nt<0><<<dim3(VV / 64, MM / 64), 256>>>(ln, wte, nullptr, nullptr, out, VV, CC);
}

// round 4
// speedup vs baseline: 2.6618x; 2.6618x over previous
#include <cuda_runtime.h>
#include <cuda_bf16.h>
#include <math.h>
#include <cstdint>

#define BB 2
#define TT 1024
#define LL 12
#define HH 12
#define CC 768
#define VV 50304
#define HD 64
#define MM (BB*TT)    // 2048 rows
#define C3 (3*CC)     // 2304
#define C4 (4*CC)     // 3072

// ---------------- scratch (static device allocations; no cudaMalloc) ----------
__device__ float g_x  [MM*CC];
__device__ float g_ln [MM*CC];
__device__ float g_qkv[MM*C3];
__device__ float g_att[(size_t)BB*HH*TT*TT];
__device__ float g_y  [MM*CC];
__device__ float g_mlp[MM*C4];

// =================== warp-level bf16x3 HMMA GEMM ===============================
// C[M,N] = A[M,K] * B[N,K]^T in ~fp32 precision via split bf16:
//   a = ah + al, b = bh + bl;  acc += ah*bh + ah*bl + al*bh  (al*bl ~ 2^-18, dropped)
// CTA tile 128x128, 8 warps (4 along M, 2 along N), warp tile 32x64,
// fragments m16n8k16. K staged in 32-wide chunks, hi/lo bf16 planes in smem.
// smem row pitch = 40 bf16 (80B) -> conflict-free quad-strided fragment loads.
// EPI bits: 1 = +bias[col]   4 = exact gelu   2 = +resid[row*N+col]

#define MMA16816(d, A0,A1,A2,A3, B0,B1) \
    asm volatile("mma.sync.aligned.m16n8k16.row.col.f32.bf16.bf16.f32 " \
        "{%0,%1,%2,%3}, {%4,%5,%6,%7}, {%8,%9}, {%0,%1,%2,%3};" \
        : "+f"((d)[0]), "+f"((d)[1]), "+f"((d)[2]), "+f"((d)[3]) \
        : "r"(A0), "r"(A1), "r"(A2), "r"(A3), "r"(B0), "r"(B1))

#define PITCHB 80                          // bytes per 32-bf16 row (40 bf16)
#define MATB   (128 * PITCHB)              // one plane: 10240 B
#define STAGEB (4 * MATB)                  // Ah|Al|Bh|Bl: 40960 B
#define GSMEM  (2 * STAGEB)                // 81920 B dynamic smem

__device__ __forceinline__ uint32_t pack_bf2(float x, float y) {
    __nv_bfloat162 h = __floats2bfloat162_rn(x, y);
    return reinterpret_cast<uint32_t&>(h);
}

// convert one staged chunk (8 float4 per thread: 4 of A, 4 of B) into smem planes
__device__ __forceinline__ void stage_store(char* stg, const float4* pre, int tid) {
#pragma unroll
    for (int i = 0; i < 8; i++) {
        int e   = tid + i * 256;          // 0..2047 float4 slots
        int isB = e >> 10;                // 0..1023 A, 1024.. B
        int r   = (e >> 3) & 127;
        int c4  = e & 7;                  // float4 index within 32-wide chunk
        float4 f = pre[i];
        float hx = __bfloat162float(__float2bfloat16_rn(f.x));
        float hy = __bfloat162float(__float2bfloat16_rn(f.y));
        float hz = __bfloat162float(__float2bfloat16_rn(f.z));
        float hw = __bfloat162float(__float2bfloat16_rn(f.w));
        uint2 hi = make_uint2(pack_bf2(f.x, f.y), pack_bf2(f.z, f.w));
        uint2 lo = make_uint2(pack_bf2(f.x - hx, f.y - hy),
                              pack_bf2(f.z - hz, f.w - hw));
        char* p = stg + isB * (2 * MATB) + r * PITCHB + c4 * 8;
        *(uint2*)(p)        = hi;
        *(uint2*)(p + MATB) = lo;
    }
}

template<int EPI>
__global__ __launch_bounds__(256) void gemm_mma(
    const float* __restrict__ A, const float* __restrict__ Bw,
    const float* __restrict__ bias, const float* __restrict__ resid,
    float* __restrict__ Cm, int N, int K)
{
    extern __shared__ __align__(1024) char dyn[];
    const int tid  = threadIdx.x;
    const int wid  = tid >> 5;
    const int lane = tid & 31;
    const int g    = lane >> 2;     // fragment "group" row
    const int tg   = lane & 3;      // thread-in-group
    const int wm   = wid & 3;       // warp M index (0..3)
    const int wn   = wid >> 2;      // warp N index (0..1)
    const int bm = blockIdx.x, bn = blockIdx.y;

    const float* Ab = A  + (size_t)bm * 128 * K;
    const float* Bb = Bw + (size_t)bn * 128 * K;
    const int nch = K >> 5;     // 32-wide K chunks

    float acc[2][8][4];
#pragma unroll
    for (int mi = 0; mi < 2; mi++)
#pragma unroll
        for (int j = 0; j < 8; j++)
#pragma unroll
            for (int q = 0; q < 4; q++) acc[mi][j][q] = 0.f;

    // ---- prologue: stage chunk 0 ----
    {
        float4 pre[8];
#pragma unroll
        for (int i = 0; i < 8; i++) {
            int e = tid + i * 256;
            int isB = e >> 10;
            int r = (e >> 3) & 127, c4 = e & 7;
            pre[i] = *(const float4*)((isB ? Bb : Ab) + (size_t)r * K + c4 * 4);
        }
        stage_store(dyn, pre, tid);
    }
    __syncthreads();

    for (int c = 0; c < nch; c++) {
        const int s = c & 1;
        const bool hasNext = (c + 1) < nch;
        float4 pre[8];
        if (hasNext) {
            const int k0n = (c + 1) << 5;
#pragma unroll
            for (int i = 0; i < 8; i++) {
                int e = tid + i * 256;
                int isB = e >> 10;
                int r = (e >> 3) & 127, c4 = e & 7;
                pre[i] = *(const float4*)((isB ? Bb : Ab) + (size_t)r * K + k0n + c4 * 4);
            }
        }

        const char* smA  = dyn + s * STAGEB;
        const char* smAl = smA + MATB;
        const char* smB  = smA + 2 * MATB;
        const char* smBl = smA + 3 * MATB;

#pragma unroll
        for (int kk = 0; kk < 2; kk++) {
            const int kb = kk * 32 + tg * 4;    // byte offset of k within row
            uint32_t a[2][4], al[2][4], b[8][2];
            // Ah fragments
#pragma unroll
            for (int mi = 0; mi < 2; mi++) {
                const char* p = smA + (wm * 32 + mi * 16 + g) * PITCHB + kb;
                a[mi][0] = *(const uint32_t*)(p);
                a[mi][1] = *(const uint32_t*)(p + 8 * PITCHB);
                a[mi][2] = *(const uint32_t*)(p + 16);
                a[mi][3] = *(const uint32_t*)(p + 8 * PITCHB + 16);
            }
            // Bh fragments
#pragma unroll
            for (int j = 0; j < 8; j++) {
                const char* p = smB + (wn * 64 + j * 8 + g) * PITCHB + kb;
                b[j][0] = *(const uint32_t*)(p);
                b[j][1] = *(const uint32_t*)(p + 16);
            }
            // hi * hi
#pragma unroll
            for (int mi = 0; mi < 2; mi++)
#pragma unroll
                for (int j = 0; j < 8; j++)
                    MMA16816(acc[mi][j], a[mi][0], a[mi][1], a[mi][2], a[mi][3],
                             b[j][0], b[j][1]);
            // lo * hi
#pragma unroll
            for (int mi = 0; mi < 2; mi++) {
                const char* p = smAl + (wm * 32 + mi * 16 + g) * PITCHB + kb;
                al[mi][0] = *(const uint32_t*)(p);
                al[mi][1] = *(const uint32_t*)(p + 8 * PITCHB);
                al[mi][2] = *(const uint32_t*)(p + 16);
                al[mi][3] = *(const uint32_t*)(p + 8 * PITCHB + 16);
            }
#pragma unroll
            for (int mi = 0; mi < 2; mi++)
#pragma unroll
                for (int j = 0; j < 8; j++)
                    MMA16816(acc[mi][j], al[mi][0], al[mi][1], al[mi][2], al[mi][3],
                             b[j][0], b[j][1]);
            // hi * lo  (reuse b regs for Bl)
#pragma unroll
            for (int j = 0; j < 8; j++) {
                const char* p = smBl + (wn * 64 + j * 8 + g) * PITCHB + kb;
                b[j][0] = *(const uint32_t*)(p);
                b[j][1] = *(const uint32_t*)(p + 16);
            }
#pragma unroll
            for (int mi = 0; mi < 2; mi++)
#pragma unroll
                for (int j = 0; j < 8; j++)
                    MMA16816(acc[mi][j], a[mi][0], a[mi][1], a[mi][2], a[mi][3],
                             b[j][0], b[j][1]);
        }
        __syncthreads();
        if (hasNext) stage_store(dyn + ((c + 1) & 1) * STAGEB, pre, tid);
        __syncthreads();
    }

    // ---- epilogue ----
#pragma unroll
    for (int mi = 0; mi < 2; mi++) {
#pragma unroll
        for (int j = 0; j < 8; j++) {
            int r0  = bm * 128 + wm * 32 + mi * 16 + g;
            int col = bn * 128 + wn * 64 + j * 8 + tg * 2;
            float v00 = acc[mi][j][0], v01 = acc[mi][j][1];
            float v10 = acc[mi][j][2], v11 = acc[mi][j][3];
            if (EPI & 1) {
                float bx = bias[col], by = bias[col + 1];
                v00 += bx; v01 += by; v10 += bx; v11 += by;
            }
            if (EPI & 4) {
                v00 = 0.5f * v00 * (1.0f + erff(v00 * 0.70710678118654752f));
                v01 = 0.5f * v01 * (1.0f + erff(v01 * 0.70710678118654752f));
                v10 = 0.5f * v10 * (1.0f + erff(v10 * 0.70710678118654752f));
                v11 = 0.5f * v11 * (1.0f + erff(v11 * 0.70710678118654752f));
            }
            size_t o0 = (size_t)r0 * N + col;
            size_t o1 = (size_t)(r0 + 8) * N + col;
            if (EPI & 2) {
                float2 r00 = *(const float2*)(resid + o0);
                float2 r11 = *(const float2*)(resid + o1);
                v00 += r00.x; v01 += r00.y; v10 += r11.x; v11 += r11.y;
            }
            *(float2*)(Cm + o0) = make_float2(v00, v01);
            *(float2*)(Cm + o1) = make_float2(v10, v11);
        }
    }
}

// ---------------- embedding ---------------------------------------------------
__global__ void embed_kernel(const int* __restrict__ idx,
                             const float* __restrict__ wte,
                             const float* __restrict__ wpe) {
    int i = blockIdx.x * blockDim.x + threadIdx.x;
    if (i >= MM * CC) return;
    int row = i / CC, c = i - row * CC;
    int t = row & (TT - 1);
    int tok = idx[row];
    g_x[i] = wte[(size_t)tok * CC + c] + wpe[(size_t)t * CC + c];
}

// ---------------- layernorm ----------------------------------------------------
__global__ __launch_bounds__(256) void ln_kernel(const float* __restrict__ in,
                                                 const float* __restrict__ w,
                                                 const float* __restrict__ b,
                                                 float* __restrict__ out) {
    int row = blockIdx.x;
    const float* x = in + (size_t)row * CC;
    int t = threadIdx.x;
    float v[3];
    float s = 0.f, s2 = 0.f;
#pragma unroll
    for (int i = 0; i < 3; i++) {
        float u = x[t + i * 256];
        v[i] = u; s += u; s2 += u * u;
    }
    __shared__ float sh[16];
#pragma unroll
    for (int o = 16; o > 0; o >>= 1) {
        s  += __shfl_down_sync(0xffffffffu, s,  o);
        s2 += __shfl_down_sync(0xffffffffu, s2, o);
    }
    int lane = t & 31, wid = t >> 5;
    if (lane == 0) { sh[wid] = s; sh[8 + wid] = s2; }
    __syncthreads();
    if (wid == 0) {
        s  = (lane < 8) ? sh[lane]     : 0.f;
        s2 = (lane < 8) ? sh[8 + lane] : 0.f;
#pragma unroll
        for (int o = 4; o > 0; o >>= 1) {
            s  += __shfl_down_sync(0xffffffffu, s,  o);
            s2 += __shfl_down_sync(0xffffffffu, s2, o);
        }
        if (lane == 0) { sh[0] = s; sh[8] = s2; }
    }
    __syncthreads();
    float mean = sh[0] * (1.0f / CC);
    float var  = sh[8] * (1.0f / CC) - mean * mean;
    float rstd = rsqrtf(var + 1e-5f);
    float* o = out + (size_t)row * CC;
#pragma unroll
    for (int i = 0; i < 3; i++) {
        int c = t + i * 256;
        o[c] = (v[i] - mean) * rstd * w[c] + b[c];
    }
}

// ---------------- attention scores: 64x64 register-tiled, live-region only ----
__global__ __launch_bounds__(256) void attn_scores(const float* __restrict__ qkv,
                                                   float* __restrict__ att) {
    int kt = blockIdx.x, qt = blockIdx.y, bh = blockIdx.z;
    int live = (((qt * 64 + 63) >> 8) + 1) * 256;   // cols < live are read later
    if (kt * 64 >= live) return;                    // never read: skip entirely
    int b = bh / HH, h = bh - b * HH;
    int tid = threadIdx.x;
    float* ablk = att + ((size_t)bh * TT + (size_t)qt * 64) * TT + kt * 64;

    if (kt > qt) {   // live but fully above diagonal: fill mask value
#pragma unroll
        for (int i = 0; i < 4; i++) {
            int e = tid + i * 256;       // 1024 float4 = 64 x 16
            int r = e >> 4, c4 = (e & 15) * 4;
            *(float4*)(ablk + (size_t)r * TT + c4) =
                make_float4(-1e30f, -1e30f, -1e30f, -1e30f);
        }
        return;
    }

    __shared__ float Qs[64][68];   // 68-float pitch: 272B, float4-aligned rows
    __shared__ float Ks[64][68];
    const float* qb = qkv + ((size_t)b * TT + qt * 64) * C3 + h * HD;
    const float* kb = qkv + ((size_t)b * TT + kt * 64) * C3 + CC + h * HD;
#pragma unroll
    for (int i = 0; i < 4; i++) {
        int e = tid + i * 256;
        int r = e >> 4, c4 = (e & 15) * 4;
        *(float4*)&Qs[r][c4] = *(const float4*)(qb + (size_t)r * C3 + c4);
        *(float4*)&Ks[r][c4] = *(const float4*)(kb + (size_t)r * C3 + c4);
    }
    __syncthreads();

    int tx = tid & 15, ty = tid >> 4;
    float acc[4][4] = {};
#pragma unroll
    for (int kk = 0; kk < HD; kk++) {
        float qf[4], kf[4];
#pragma unroll
        for (int i = 0; i < 4; i++) qf[i] = Qs[ty + i * 16][kk];
#pragma unroll
        for (int j = 0; j < 4; j++) kf[j] = Ks[tx + j * 16][kk];
#pragma unroll
        for (int i = 0; i < 4; i++)
#pragma unroll
            for (int j = 0; j < 4; j++)
                acc[i][j] += qf[i] * kf[j];
    }
#pragma unroll
    for (int i = 0; i < 4; i++) {
        int q = qt * 64 + ty + i * 16;
#pragma unroll
        for (int j = 0; j < 4; j++) {
            int k = kt * 64 + tx + j * 16;
            ablk[(size_t)(ty + i * 16) * TT + tx + j * 16] =
                (k <= q) ? acc[i][j] * 0.125f : -1e30f;
        }
    }
}

// ---------------- row softmax, triangle-aware ----------------------------------
__global__ __launch_bounds__(256) void softmax_rows(float* __restrict__ att) {
    float* a = att + (size_t)blockIdx.x * TT;
    int q = blockIdx.x & (TT - 1);
    int nch = (q >> 8) + 1;
    int t = threadIdx.x;
    float v[4];
    float mx = -1e30f;
#pragma unroll
    for (int i = 0; i < 4; i++) {
        v[i] = (i < nch) ? a[t + i * 256] : -1e30f;
        mx = fmaxf(mx, v[i]);
    }
    __shared__ float sh[8];
#pragma unroll
    for (int o = 16; o > 0; o >>= 1) mx = fmaxf(mx, __shfl_xor_sync(0xffffffffu, mx, o));
    int lane = t & 31, wid = t >> 5;
    if (lane == 0) sh[wid] = mx;
    __syncthreads();
    mx = fmaxf(fmaxf(fmaxf(sh[0], sh[1]), fmaxf(sh[2], sh[3])),
               fmaxf(fmaxf(sh[4], sh[5]), fmaxf(sh[6], sh[7])));
    float s = 0.f;
#pragma unroll
    for (int i = 0; i < 4; i++) { v[i] = expf(v[i] - mx); s += v[i]; }
#pragma unroll
    for (int o = 16; o > 0; o >>= 1) s += __shfl_xor_sync(0xffffffffu, s, o);
    __syncthreads();
    if (lane == 0) sh[wid] = s;
    __syncthreads();
    s = sh[0] + sh[1] + sh[2] + sh[3] + sh[4] + sh[5] + sh[6] + sh[7];
    float inv = 1.0f / s;
#pragma unroll
    for (int i = 0; i < 4; i++)
        if (i < nch) a[t + i * 256] = v[i] * inv;
}

// ---------------- AV (triangle-limited) ----------------------------------------
__global__ __launch_bounds__(256) void attn_av(const float* __restrict__ att,
                                               const float* __restrict__ qkv,
                                               float* __restrict__ yout) {
    int qt = blockIdx.x, bh = blockIdx.y;
    int b = bh / HH, h = bh - b * HH;
    __shared__ float As[64][17];
    __shared__ float Bs[16][64];
    int tid = threadIdx.x;
    int tx = tid & 15, ty = tid >> 4;
    const float* abase = att + ((size_t)bh * TT + (size_t)qt * 64) * TT;
    const float* vbase = qkv + ((size_t)b * TT) * C3 + 2 * CC + h * HD;
    int lr = tid >> 2;
    int lc = (tid & 3) * 4;
    int vk = tid >> 6;
    int vd = tid & 63;

    float acc[4][4] = {};
    const int kmax = (qt + 1) * 64;
    for (int k0 = 0; k0 < kmax; k0 += 16) {
        float4 a4 = *(const float4*)(abase + (size_t)lr * TT + k0 + lc);
        As[lr][lc] = a4.x; As[lr][lc+1] = a4.y; As[lr][lc+2] = a4.z; As[lr][lc+3] = a4.w;
#pragma unroll
        for (int i = 0; i < 4; i++)
            Bs[vk + i * 4][vd] = vbase[(size_t)(k0 + vk + i * 4) * C3 + vd];
        __syncthreads();
#pragma unroll
        for (int kk = 0; kk < 16; kk++) {
            float af[4], bf[4];
#pragma unroll
            for (int i = 0; i < 4; i++) af[i] = As[ty * 4 + i][kk];
#pragma unroll
            for (int j = 0; j < 4; j++) bf[j] = Bs[kk][tx * 4 + j];
#pragma unroll
            for (int i = 0; i < 4; i++)
#pragma unroll
                for (int j = 0; j < 4; j++)
                    acc[i][j] += af[i] * bf[j];
        }
        __syncthreads();
    }
#pragma unroll
    for (int i = 0; i < 4; i++) {
        int t = qt * 64 + ty * 4 + i;
#pragma unroll
        for (int j = 0; j < 4; j++)
            yout[((size_t)b * TT + t) * CC + h * HD + tx * 4 + j] = acc[i][j];
    }
}

// ---------------- host orchestration ------------------------------------------
extern "C" void kernel_launch(void* const* d_in, const int* in_sizes, int n_in,
                              void* d_out, int out_size) {
    (void)in_sizes; (void)n_in; (void)out_size;
    const int*   idx          = (const int*)  d_in[0];
    const float* wte          = (const float*)d_in[1];
    const float* wpe          = (const float*)d_in[2];
    const float* ln1_w        = (const float*)d_in[3];
    const float* ln1_b        = (const float*)d_in[4];
    const float* attn_w       = (const float*)d_in[5];
    const float* attn_b       = (const float*)d_in[6];
    const float* attn_proj_w  = (const float*)d_in[7];
    const float* attn_proj_b  = (const float*)d_in[8];
    const float* ln2_w        = (const float*)d_in[9];
    const float* ln2_b        = (const float*)d_in[10];
    const float* fc_w         = (const float*)d_in[11];
    const float* fc_b         = (const float*)d_in[12];
    const float* mlp_proj_w   = (const float*)d_in[13];
    const float* mlp_proj_b   = (const float*)d_in[14];
    const float* lnf_w        = (const float*)d_in[15];
    const float* lnf_b        = (const float*)d_in[16];
    float* out = (float*)d_out;

    float *x, *ln, *qkv, *att, *y, *mlp;
    cudaGetSymbolAddress((void**)&x,   g_x);
    cudaGetSymbolAddress((void**)&ln,  g_ln);
    cudaGetSymbolAddress((void**)&qkv, g_qkv);
    cudaGetSymbolAddress((void**)&att, g_att);
    cudaGetSymbolAddress((void**)&y,   g_y);
    cudaGetSymbolAddress((void**)&mlp, g_mlp);

    cudaFuncSetAttribute(gemm_mma<0>, cudaFuncAttributeMaxDynamicSharedMemorySize, GSMEM);
    cudaFuncSetAttribute(gemm_mma<1>, cudaFuncAttributeMaxDynamicSharedMemorySize, GSMEM);
    cudaFuncSetAttribute(gemm_mma<3>, cudaFuncAttributeMaxDynamicSharedMemorySize, GSMEM);
    cudaFuncSetAttribute(gemm_mma<5>, cudaFuncAttributeMaxDynamicSharedMemorySize, GSMEM);

    embed_kernel<<<(MM * CC + 255) / 256, 256>>>(idx, wte, wpe);

    for (int l = 0; l < LL; l++) {
        ln_kernel<<<MM, 256>>>(x, ln1_w + l * CC, ln1_b + l * CC, ln);
        gemm_mma<1><<<dim3(MM / 128, C3 / 128), 256, GSMEM>>>(
            ln, attn_w + (size_t)l * C3 * CC, attn_b + l * C3, nullptr, qkv, C3, CC);
        attn_scores<<<dim3(TT / 64, TT / 64, BB * HH), 256>>>(qkv, att);
        softmax_rows<<<BB * HH * TT, 256>>>(att);
        attn_av<<<dim3(TT / 64, BB * HH), 256>>>(att, qkv, y);
        gemm_mma<3><<<dim3(MM / 128, CC / 128), 256, GSMEM>>>(
            y, attn_proj_w + (size_t)l * CC * CC, attn_proj_b + l * CC, x, x, CC, CC);
        ln_kernel<<<MM, 256>>>(x, ln2_w + l * CC, ln2_b + l * CC, ln);
        gemm_mma<5><<<dim3(MM / 128, C4 / 128), 256, GSMEM>>>(
            ln, fc_w + (size_t)l * C4 * CC, fc_b + l * C4, nullptr, mlp, C4, CC);
        gemm_mma<3><<<dim3(MM / 128, CC / 128), 256, GSMEM>>>(
            mlp, mlp_proj_w + (size_t)l * CC * C4, mlp_proj_b + l * CC, x, x, CC, C4);
    }

    ln_kernel<<<MM, 256>>>(x, lnf_w, lnf_b, ln);
    gemm_mma<0><<<dim3(MM / 128, VV / 128), 256, GSMEM>>>(
        ln, wte, nullptr, nullptr, out, VV, CC);
}

// round 5
// speedup vs baseline: 3.0699x; 1.1533x over previous
#include <cuda_runtime.h>
#include <cuda_bf16.h>
#include <math.h>
#include <cstdint>

#define BB 2
#define TT 1024
#define LL 12
#define HH 12
#define CC 768
#define VV 50304
#define HD 64
#define MM (BB*TT)    // 2048 rows
#define C3 (3*CC)     // 2304
#define C4 (4*CC)     // 3072

// ---------------- scratch (static device allocations; no cudaMalloc) ----------
__device__ float g_x[MM*CC];                         // residual stream (fp32)
// activation bf16 hi/lo planes
__device__ __nv_bfloat16 g_lnh[MM*CC],  g_lnl[MM*CC];
__device__ __nv_bfloat16 g_qkvh[MM*C3], g_qkvl[MM*C3];
__device__ __nv_bfloat16 g_yh[MM*CC],   g_yl[MM*CC];
__device__ __nv_bfloat16 g_mlph[MM*C4], g_mlpl[MM*C4];
// weight bf16 hi/lo planes (converted once per forward)
__device__ __nv_bfloat16 g_wteh[(size_t)VV*CC], g_wtel[(size_t)VV*CC];
__device__ __nv_bfloat16 g_awh[(size_t)LL*C3*CC], g_awl[(size_t)LL*C3*CC];
__device__ __nv_bfloat16 g_aph[(size_t)LL*CC*CC], g_apl[(size_t)LL*CC*CC];
__device__ __nv_bfloat16 g_fch[(size_t)LL*C4*CC], g_fcl[(size_t)LL*C4*CC];
__device__ __nv_bfloat16 g_mph[(size_t)LL*CC*C4], g_mpl[(size_t)LL*CC*C4];

// =================== common helpers ============================================
__device__ __forceinline__ uint32_t smem_u32(const void* p) {
    uint32_t a;
    asm("{ .reg .u64 t; cvta.to.shared.u64 t, %1; cvt.u32.u64 %0, t; }"
        : "=r"(a) : "l"(p));
    return a;
}

#define MMA16816(d, A0,A1,A2,A3, B0,B1) \
    asm volatile("mma.sync.aligned.m16n8k16.row.col.f32.bf16.bf16.f32 " \
        "{%0,%1,%2,%3}, {%4,%5,%6,%7}, {%8,%9}, {%0,%1,%2,%3};" \
        : "+f"((d)[0]), "+f"((d)[1]), "+f"((d)[2]), "+f"((d)[3]) \
        : "r"(A0), "r"(A1), "r"(A2), "r"(A3), "r"(B0), "r"(B1))

#define CP_ASYNC16(saddr, gptr) \
    asm volatile("cp.async.cg.shared.global [%0], [%1], 16;" \
        :: "r"(saddr), "l"(gptr) : "memory")
#define CP_COMMIT() asm volatile("cp.async.commit_group;" ::: "memory")
#define CP_WAIT(n)  asm volatile("cp.async.wait_group %0;" :: "n"(n) : "memory")

__device__ __forceinline__ uint32_t pack_bf2(float x, float y) {
    __nv_bfloat162 h = __floats2bfloat162_rn(x, y);
    return reinterpret_cast<uint32_t&>(h);
}
__device__ __forceinline__ void split_bf(float v, __nv_bfloat16& h, __nv_bfloat16& l) {
    h = __float2bfloat16_rn(v);
    l = __float2bfloat16_rn(v - __bfloat162float(h));
}

// ---------------- fp32 -> bf16 hi/lo plane conversion (vectorized) -------------
__global__ void convert_planes(const float* __restrict__ src,
                               __nv_bfloat16* __restrict__ hi,
                               __nv_bfloat16* __restrict__ lo, int n4) {
    int i = blockIdx.x * blockDim.x + threadIdx.x;
    if (i >= n4) return;
    float4 f = ((const float4*)src)[i];
    float hx = __bfloat162float(__float2bfloat16_rn(f.x));
    float hy = __bfloat162float(__float2bfloat16_rn(f.y));
    float hz = __bfloat162float(__float2bfloat16_rn(f.z));
    float hw = __bfloat162float(__float2bfloat16_rn(f.w));
    ((uint2*)hi)[i] = make_uint2(pack_bf2(f.x, f.y), pack_bf2(f.z, f.w));
    ((uint2*)lo)[i] = make_uint2(pack_bf2(f.x - hx, f.y - hy),
                                 pack_bf2(f.z - hz, f.w - hw));
}

// =================== bf16x3 HMMA GEMM on pre-split planes ======================
// C = A * B^T.  A,B given as bf16 hi/lo planes [rows][K].
// CTA 128x128, 8 warps (4M x 2N), warp 32x64, BK=32 chunks via cp.async (2-stage).
// EPI bits: 1=+bias  2=+resid(fp32 out)  4=gelu  8=emit hi/lo planes (else fp32)
#define PITCHB 80
#define MATB   (128 * PITCHB)     // 10240 B per plane
#define STAGEB (4 * MATB)         // Ah|Al|Bh|Bl: 40960 B
#define GSMEM  (2 * STAGEB)       // 81920 B

__device__ __forceinline__ void issue_cp(uint32_t dst0,
    const __nv_bfloat16* a0, const __nv_bfloat16* a1,
    const __nv_bfloat16* b0, const __nv_bfloat16* b1,
    int K, int k0, int tid)
{
    const __nv_bfloat16* gs[4] = {a0, a1, b0, b1};
    int r_lo = tid >> 2, c16 = tid & 3;
#pragma unroll
    for (int i = 0; i < 8; i++) {
        int p = i >> 1;
        int r = (i & 1) * 64 + r_lo;
        const __nv_bfloat16* g = gs[p] + (size_t)r * K + k0 + c16 * 8;
        CP_ASYNC16(dst0 + p * MATB + r * PITCHB + c16 * 16, g);
    }
}

template<int EPI>
__global__ __launch_bounds__(256, 2) void gemm_mma(
    const __nv_bfloat16* __restrict__ Ah, const __nv_bfloat16* __restrict__ Al,
    const __nv_bfloat16* __restrict__ Bh, const __nv_bfloat16* __restrict__ Bl,
    const float* __restrict__ bias, const float* __restrict__ resid,
    float* __restrict__ Cf, __nv_bfloat16* __restrict__ Ch,
    __nv_bfloat16* __restrict__ Cl, int N, int K)
{
    extern __shared__ __align__(1024) char dyn[];
    const int tid  = threadIdx.x;
    const int wid  = tid >> 5;
    const int lane = tid & 31;
    const int g    = lane >> 2;
    const int tg   = lane & 3;
    const int wm   = wid & 3;
    const int wn   = wid >> 2;
    const int bm = blockIdx.x, bn = blockIdx.y;

    const __nv_bfloat16* A0 = Ah + (size_t)bm * 128 * K;
    const __nv_bfloat16* A1 = Al + (size_t)bm * 128 * K;
    const __nv_bfloat16* B0 = Bh + (size_t)bn * 128 * K;
    const __nv_bfloat16* B1 = Bl + (size_t)bn * 128 * K;
    const int nch = K >> 5;
    const uint32_t sm0 = smem_u32(dyn);

    float acc[2][8][4];
#pragma unroll
    for (int mi = 0; mi < 2; mi++)
#pragma unroll
        for (int j = 0; j < 8; j++)
#pragma unroll
            for (int q = 0; q < 4; q++) acc[mi][j][q] = 0.f;

    issue_cp(sm0, A0, A1, B0, B1, K, 0, tid);
    CP_COMMIT();

    for (int c = 0; c < nch; c++) {
        const int s = c & 1;
        if (c + 1 < nch) {
            issue_cp(sm0 + ((c + 1) & 1) * STAGEB, A0, A1, B0, B1,
                     K, (c + 1) << 5, tid);
            CP_COMMIT();
            CP_WAIT(1);
        } else {
            CP_WAIT(0);
        }
        __syncthreads();

        const char* smA  = dyn + s * STAGEB;
        const char* smAl = smA + MATB;
        const char* smB  = smA + 2 * MATB;
        const char* smBl = smA + 3 * MATB;

#pragma unroll
        for (int kk = 0; kk < 2; kk++) {
            const int kb = kk * 32 + tg * 4;
            uint32_t a[2][4], al[2][4], b[8][2];
#pragma unroll
            for (int mi = 0; mi < 2; mi++) {
                const char* p = smA + (wm * 32 + mi * 16 + g) * PITCHB + kb;
                a[mi][0] = *(const uint32_t*)(p);
                a[mi][1] = *(const uint32_t*)(p + 8 * PITCHB);
                a[mi][2] = *(const uint32_t*)(p + 16);
                a[mi][3] = *(const uint32_t*)(p + 8 * PITCHB + 16);
            }
#pragma unroll
            for (int j = 0; j < 8; j++) {
                const char* p = smB + (wn * 64 + j * 8 + g) * PITCHB + kb;
                b[j][0] = *(const uint32_t*)(p);
                b[j][1] = *(const uint32_t*)(p + 16);
            }
#pragma unroll
            for (int mi = 0; mi < 2; mi++)
#pragma unroll
                for (int j = 0; j < 8; j++)
                    MMA16816(acc[mi][j], a[mi][0], a[mi][1], a[mi][2], a[mi][3],
                             b[j][0], b[j][1]);
#pragma unroll
            for (int mi = 0; mi < 2; mi++) {
                const char* p = smAl + (wm * 32 + mi * 16 + g) * PITCHB + kb;
                al[mi][0] = *(const uint32_t*)(p);
                al[mi][1] = *(const uint32_t*)(p + 8 * PITCHB);
                al[mi][2] = *(const uint32_t*)(p + 16);
                al[mi][3] = *(const uint32_t*)(p + 8 * PITCHB + 16);
            }
#pragma unroll
            for (int mi = 0; mi < 2; mi++)
#pragma unroll
                for (int j = 0; j < 8; j++)
                    MMA16816(acc[mi][j], al[mi][0], al[mi][1], al[mi][2], al[mi][3],
                             b[j][0], b[j][1]);
#pragma unroll
            for (int j = 0; j < 8; j++) {
                const char* p = smBl + (wn * 64 + j * 8 + g) * PITCHB + kb;
                b[j][0] = *(const uint32_t*)(p);
                b[j][1] = *(const uint32_t*)(p + 16);
            }
#pragma unroll
            for (int mi = 0; mi < 2; mi++)
#pragma unroll
                for (int j = 0; j < 8; j++)
                    MMA16816(acc[mi][j], a[mi][0], a[mi][1], a[mi][2], a[mi][3],
                             b[j][0], b[j][1]);
        }
        __syncthreads();
    }

    // ---- epilogue ----
#pragma unroll
    for (int mi = 0; mi < 2; mi++) {
#pragma unroll
        for (int j = 0; j < 8; j++) {
            int r0  = bm * 128 + wm * 32 + mi * 16 + g;
            int col = bn * 128 + wn * 64 + j * 8 + tg * 2;
            float v00 = acc[mi][j][0], v01 = acc[mi][j][1];
            float v10 = acc[mi][j][2], v11 = acc[mi][j][3];
            if (EPI & 1) {
                float bx = bias[col], by = bias[col + 1];
                v00 += bx; v01 += by; v10 += bx; v11 += by;
            }
            if (EPI & 4) {
                v00 = 0.5f * v00 * (1.0f + erff(v00 * 0.70710678118654752f));
                v01 = 0.5f * v01 * (1.0f + erff(v01 * 0.70710678118654752f));
                v10 = 0.5f * v10 * (1.0f + erff(v10 * 0.70710678118654752f));
                v11 = 0.5f * v11 * (1.0f + erff(v11 * 0.70710678118654752f));
            }
            size_t o0 = (size_t)r0 * N + col;
            size_t o1 = (size_t)(r0 + 8) * N + col;
            if (EPI & 8) {
                float h00 = __bfloat162float(__float2bfloat16_rn(v00));
                float h01 = __bfloat162float(__float2bfloat16_rn(v01));
                float h10 = __bfloat162float(__float2bfloat16_rn(v10));
                float h11 = __bfloat162float(__float2bfloat16_rn(v11));
                *(uint32_t*)(Ch + o0) = pack_bf2(v00, v01);
                *(uint32_t*)(Ch + o1) = pack_bf2(v10, v11);
                *(uint32_t*)(Cl + o0) = pack_bf2(v00 - h00, v01 - h01);
                *(uint32_t*)(Cl + o1) = pack_bf2(v10 - h10, v11 - h11);
            } else {
                if (EPI & 2) {
                    float2 r00 = *(const float2*)(resid + o0);
                    float2 r11 = *(const float2*)(resid + o1);
                    v00 += r00.x; v01 += r00.y; v10 += r11.x; v11 += r11.y;
                }
                *(float2*)(Cf + o0) = make_float2(v00, v01);
                *(float2*)(Cf + o1) = make_float2(v10, v11);
            }
        }
    }
}

// ---------------- embedding ---------------------------------------------------
__global__ void embed_kernel(const int* __restrict__ idx,
                             const float* __restrict__ wte,
                             const float* __restrict__ wpe) {
    int i = blockIdx.x * blockDim.x + threadIdx.x;
    if (i >= MM * CC) return;
    int row = i / CC, c = i - row * CC;
    int t = row & (TT - 1);
    int tok = idx[row];
    g_x[i] = wte[(size_t)tok * CC + c] + wpe[(size_t)t * CC + c];
}

// ---------------- layernorm: fp32 in -> bf16 hi/lo planes out ------------------
__global__ __launch_bounds__(256) void ln_kernel(const float* __restrict__ in,
                                                 const float* __restrict__ w,
                                                 const float* __restrict__ b,
                                                 __nv_bfloat16* __restrict__ oh,
                                                 __nv_bfloat16* __restrict__ ol) {
    int row = blockIdx.x;
    const float* x = in + (size_t)row * CC;
    int t = threadIdx.x;
    float v[3];
    float s = 0.f, s2 = 0.f;
#pragma unroll
    for (int i = 0; i < 3; i++) {
        float u = x[t + i * 256];
        v[i] = u; s += u; s2 += u * u;
    }
    __shared__ float sh[16];
#pragma unroll
    for (int o = 16; o > 0; o >>= 1) {
        s  += __shfl_down_sync(0xffffffffu, s,  o);
        s2 += __shfl_down_sync(0xffffffffu, s2, o);
    }
    int lane = t & 31, wid = t >> 5;
    if (lane == 0) { sh[wid] = s; sh[8 + wid] = s2; }
    __syncthreads();
    if (wid == 0) {
        s  = (lane < 8) ? sh[lane]     : 0.f;
        s2 = (lane < 8) ? sh[8 + lane] : 0.f;
#pragma unroll
        for (int o = 4; o > 0; o >>= 1) {
            s  += __shfl_down_sync(0xffffffffu, s,  o);
            s2 += __shfl_down_sync(0xffffffffu, s2, o);
        }
        if (lane == 0) { sh[0] = s; sh[8] = s2; }
    }
    __syncthreads();
    float mean = sh[0] * (1.0f / CC);
    float var  = sh[8] * (1.0f / CC) - mean * mean;
    float rstd = rsqrtf(var + 1e-5f);
#pragma unroll
    for (int i = 0; i < 3; i++) {
        int c = t + i * 256;
        float val = (v[i] - mean) * rstd * w[c] + b[c];
        __nv_bfloat16 h, l;
        split_bf(val, h, l);
        oh[(size_t)row * CC + c] = h;
        ol[(size_t)row * CC + c] = l;
    }
}

// =================== fused flash attention (bf16x3 HMMA) =======================
// grid (16 qtiles, BB*HH), 128 threads = 4 warps x 16 q-rows.
// Reads qkv planes, writes y planes. Online softmax in fp32 registers.
__global__ __launch_bounds__(128) void flash_attn(
    const __nv_bfloat16* __restrict__ qh, const __nv_bfloat16* __restrict__ ql,
    __nv_bfloat16* __restrict__ yh, __nv_bfloat16* __restrict__ yl)
{
    const int qt = (gridDim.x - 1) - blockIdx.x;     // heavy tiles first
    const int bh = blockIdx.y;
    const int b = bh / HH, h = bh - b * HH;
    const int tid = threadIdx.x, wq = tid >> 5, lane = tid & 31;
    const int g = lane >> 2, tg = lane & 3;

    __shared__ __nv_bfloat16 Kh[64][72], Kl[64][72];   // [key][d], pitch 144B
    __shared__ __nv_bfloat16 Vh[64][72], Vl[64][72];   // transposed [d][key]

    // Q fragments (row block wq*16), held across k-tiles
    uint32_t Qh[4][4], Ql[4][4];
    {
        const __nv_bfloat16* qbh = qh + ((size_t)(b * TT + qt * 64 + wq * 16)) * C3 + h * HD;
        const __nv_bfloat16* qbl = ql + ((size_t)(b * TT + qt * 64 + wq * 16)) * C3 + h * HD;
#pragma unroll
        for (int kk = 0; kk < 4; kk++) {
            int c0 = kk * 16 + tg * 2;
            Qh[kk][0] = *(const uint32_t*)(qbh + (size_t)g * C3 + c0);
            Qh[kk][1] = *(const uint32_t*)(qbh + (size_t)(g + 8) * C3 + c0);
            Qh[kk][2] = *(const uint32_t*)(qbh + (size_t)g * C3 + c0 + 8);
            Qh[kk][3] = *(const uint32_t*)(qbh + (size_t)(g + 8) * C3 + c0 + 8);
            Ql[kk][0] = *(const uint32_t*)(qbl + (size_t)g * C3 + c0);
            Ql[kk][1] = *(const uint32_t*)(qbl + (size_t)(g + 8) * C3 + c0);
            Ql[kk][2] = *(const uint32_t*)(qbl + (size_t)g * C3 + c0 + 8);
            Ql[kk][3] = *(const uint32_t*)(qbl + (size_t)(g + 8) * C3 + c0 + 8);
        }
    }

    float m0 = -1e30f, m1 = -1e30f, l0 = 0.f, l1 = 0.f;
    float O[8][4];
#pragma unroll
    for (int j = 0; j < 8; j++)
#pragma unroll
        for (int q = 0; q < 4; q++) O[j][q] = 0.f;

    for (int kt = 0; kt <= qt; kt++) {
        __syncthreads();   // previous iteration's smem reads done
        // stage K tile [key][d]
#pragma unroll
        for (int i = 0; i < 4; i++) {
            int e = tid + i * 128;
            int r = e >> 3, c16 = e & 7;
            size_t go = ((size_t)(b * TT + kt * 64 + r)) * C3 + CC + h * HD + c16 * 8;
            *(uint4*)&Kh[r][c16 * 8] = *(const uint4*)(qh + go);
            *(uint4*)&Kl[r][c16 * 8] = *(const uint4*)(ql + go);
        }
        // stage V transposed [d][key]
#pragma unroll
        for (int i = 0; i < 4; i++) {
            int e = tid + i * 128;
            int key = e & 63, dblk = e >> 6;
            size_t go = ((size_t)(b * TT + kt * 64 + key)) * C3 + 2 * CC + h * HD + dblk * 8;
            uint4 vh4 = *(const uint4*)(qh + go);
            uint4 vl4 = *(const uint4*)(ql + go);
            const __nv_bfloat16* ph = (const __nv_bfloat16*)&vh4;
            const __nv_bfloat16* pl = (const __nv_bfloat16*)&vl4;
#pragma unroll
            for (int q = 0; q < 8; q++) {
                Vh[dblk * 8 + q][key] = ph[q];
                Vl[dblk * 8 + q][key] = pl[q];
            }
        }
        __syncthreads();

        // S = Q K^T (bf16x3)
        float S[8][4];
#pragma unroll
        for (int j = 0; j < 8; j++)
#pragma unroll
            for (int q = 0; q < 4; q++) S[j][q] = 0.f;
#pragma unroll
        for (int kk = 0; kk < 4; kk++) {
#pragma unroll
            for (int j = 0; j < 8; j++) {
                int rK = j * 8 + g, cb = kk * 16 + tg * 2;
                uint32_t B0 = *(const uint32_t*)&Kh[rK][cb];
                uint32_t B1 = *(const uint32_t*)&Kh[rK][cb + 8];
                uint32_t C0 = *(const uint32_t*)&Kl[rK][cb];
                uint32_t C1 = *(const uint32_t*)&Kl[rK][cb + 8];
                MMA16816(S[j], Qh[kk][0], Qh[kk][1], Qh[kk][2], Qh[kk][3], B0, B1);
                MMA16816(S[j], Ql[kk][0], Ql[kk][1], Ql[kk][2], Ql[kk][3], B0, B1);
                MMA16816(S[j], Qh[kk][0], Qh[kk][1], Qh[kk][2], Qh[kk][3], C0, C1);
            }
        }

        // scale + causal mask (diagonal tile only)
        const int row0 = wq * 16 + g, row1 = row0 + 8;
#pragma unroll
        for (int j = 0; j < 8; j++) {
            int cl = j * 8 + tg * 2;
            S[j][0] *= 0.125f; S[j][1] *= 0.125f;
            S[j][2] *= 0.125f; S[j][3] *= 0.125f;
            if (kt == qt) {
                if (cl     > row0) S[j][0] = -1e30f;
                if (cl + 1 > row0) S[j][1] = -1e30f;
                if (cl     > row1) S[j][2] = -1e30f;
                if (cl + 1 > row1) S[j][3] = -1e30f;
            }
        }
        // row max (frags then quad shuffle)
        float mn0 = m0, mn1 = m1;
#pragma unroll
        for (int j = 0; j < 8; j++) {
            mn0 = fmaxf(mn0, fmaxf(S[j][0], S[j][1]));
            mn1 = fmaxf(mn1, fmaxf(S[j][2], S[j][3]));
        }
        mn0 = fmaxf(mn0, __shfl_xor_sync(0xffffffffu, mn0, 1));
        mn0 = fmaxf(mn0, __shfl_xor_sync(0xffffffffu, mn0, 2));
        mn1 = fmaxf(mn1, __shfl_xor_sync(0xffffffffu, mn1, 1));
        mn1 = fmaxf(mn1, __shfl_xor_sync(0xffffffffu, mn1, 2));
        float sc0 = __expf(m0 - mn0), sc1 = __expf(m1 - mn1);
        m0 = mn0; m1 = mn1;

        // P = exp(S - m), split hi/lo, row sums
        uint32_t PH0[8], PH1[8], PL0[8], PL1[8];
        float rs0 = 0.f, rs1 = 0.f;
#pragma unroll
        for (int j = 0; j < 8; j++) {
            float p0 = __expf(S[j][0] - mn0), p1 = __expf(S[j][1] - mn0);
            float p2 = __expf(S[j][2] - mn1), p3 = __expf(S[j][3] - mn1);
            rs0 += p0 + p1; rs1 += p2 + p3;
            float h0 = __bfloat162float(__float2bfloat16_rn(p0));
            float h1 = __bfloat162float(__float2bfloat16_rn(p1));
            float h2 = __bfloat162float(__float2bfloat16_rn(p2));
            float h3 = __bfloat162float(__float2bfloat16_rn(p3));
            PH0[j] = pack_bf2(p0, p1);  PH1[j] = pack_bf2(p2, p3);
            PL0[j] = pack_bf2(p0 - h0, p1 - h1);
            PL1[j] = pack_bf2(p2 - h2, p3 - h3);
        }
        rs0 += __shfl_xor_sync(0xffffffffu, rs0, 1);
        rs0 += __shfl_xor_sync(0xffffffffu, rs0, 2);
        rs1 += __shfl_xor_sync(0xffffffffu, rs1, 1);
        rs1 += __shfl_xor_sync(0xffffffffu, rs1, 2);
        l0 = l0 * sc0 + rs0;
        l1 = l1 * sc1 + rs1;

        // rescale O, then O += P V (bf16x3)
#pragma unroll
        for (int j = 0; j < 8; j++) {
            O[j][0] *= sc0; O[j][1] *= sc0;
            O[j][2] *= sc1; O[j][3] *= sc1;
        }
#pragma unroll
        for (int t = 0; t < 4; t++) {
            uint32_t ah0 = PH0[2*t], ah1 = PH1[2*t], ah2 = PH0[2*t+1], ah3 = PH1[2*t+1];
            uint32_t al0 = PL0[2*t], al1 = PL1[2*t], al2 = PL0[2*t+1], al3 = PL1[2*t+1];
#pragma unroll
            for (int jd = 0; jd < 8; jd++) {
                int rD = jd * 8 + g, cb = t * 16 + tg * 2;
                uint32_t B0 = *(const uint32_t*)&Vh[rD][cb];
                uint32_t B1 = *(const uint32_t*)&Vh[rD][cb + 8];
                uint32_t C0 = *(const uint32_t*)&Vl[rD][cb];
                uint32_t C1 = *(const uint32_t*)&Vl[rD][cb + 8];
                MMA16816(O[jd], ah0, ah1, ah2, ah3, B0, B1);
                MMA16816(O[jd], al0, al1, al2, al3, B0, B1);
                MMA16816(O[jd], ah0, ah1, ah2, ah3, C0, C1);
            }
        }
    }

    // finalize and store y planes
    float inv0 = 1.0f / l0, inv1 = 1.0f / l1;
    int t0 = qt * 64 + wq * 16 + g;
    size_t base0 = ((size_t)(b * TT) + t0) * CC + h * HD;
    size_t base1 = base0 + (size_t)8 * CC;
#pragma unroll
    for (int jd = 0; jd < 8; jd++) {
        int d = jd * 8 + tg * 2;
        float v0 = O[jd][0] * inv0, v1 = O[jd][1] * inv0;
        float v2 = O[jd][2] * inv1, v3 = O[jd][3] * inv1;
        float h0 = __bfloat162float(__float2bfloat16_rn(v0));
        float h1 = __bfloat162float(__float2bfloat16_rn(v1));
        float h2 = __bfloat162float(__float2bfloat16_rn(v2));
        float h3 = __bfloat162float(__float2bfloat16_rn(v3));
        *(uint32_t*)(yh + base0 + d) = pack_bf2(v0, v1);
        *(uint32_t*)(yh + base1 + d) = pack_bf2(v2, v3);
        *(uint32_t*)(yl + base0 + d) = pack_bf2(v0 - h0, v1 - h1);
        *(uint32_t*)(yl + base1 + d) = pack_bf2(v2 - h2, v3 - h3);
    }
}

// ---------------- host orchestration ------------------------------------------
extern "C" void kernel_launch(void* const* d_in, const int* in_sizes, int n_in,
                              void* d_out, int out_size) {
    (void)in_sizes; (void)n_in; (void)out_size;
    const int*   idx          = (const int*)  d_in[0];
    const float* wte          = (const float*)d_in[1];
    const float* wpe          = (const float*)d_in[2];
    const float* ln1_w        = (const float*)d_in[3];
    const float* ln1_b        = (const float*)d_in[4];
    const float* attn_w       = (const float*)d_in[5];
    const float* attn_b       = (const float*)d_in[6];
    const float* attn_proj_w  = (const float*)d_in[7];
    const float* attn_proj_b  = (const float*)d_in[8];
    const float* ln2_w        = (const float*)d_in[9];
    const float* ln2_b        = (const float*)d_in[10];
    const float* fc_w         = (const float*)d_in[11];
    const float* fc_b         = (const float*)d_in[12];
    const float* mlp_proj_w   = (const float*)d_in[13];
    const float* mlp_proj_b   = (const float*)d_in[14];
    const float* lnf_w        = (const float*)d_in[15];
    const float* lnf_b        = (const float*)d_in[16];
    float* out = (float*)d_out;

    float* x;
    __nv_bfloat16 *lnh, *lnl, *qkvh, *qkvl, *yh, *yl, *mlph, *mlpl;
    __nv_bfloat16 *wteh, *wtel, *awh, *awl, *aph, *apl, *fch, *fcl, *mph, *mpl;
    cudaGetSymbolAddress((void**)&x,    g_x);
    cudaGetSymbolAddress((void**)&lnh,  g_lnh);   cudaGetSymbolAddress((void**)&lnl,  g_lnl);
    cudaGetSymbolAddress((void**)&qkvh, g_qkvh);  cudaGetSymbolAddress((void**)&qkvl, g_qkvl);
    cudaGetSymbolAddress((void**)&yh,   g_yh);    cudaGetSymbolAddress((void**)&yl,   g_yl);
    cudaGetSymbolAddress((void**)&mlph, g_mlph);  cudaGetSymbolAddress((void**)&mlpl, g_mlpl);
    cudaGetSymbolAddress((void**)&wteh, g_wteh);  cudaGetSymbolAddress((void**)&wtel, g_wtel);
    cudaGetSymbolAddress((void**)&awh,  g_awh);   cudaGetSymbolAddress((void**)&awl,  g_awl);
    cudaGetSymbolAddress((void**)&aph,  g_aph);   cudaGetSymbolAddress((void**)&apl,  g_apl);
    cudaGetSymbolAddress((void**)&fch,  g_fch);   cudaGetSymbolAddress((void**)&fcl,  g_fcl);
    cudaGetSymbolAddress((void**)&mph,  g_mph);   cudaGetSymbolAddress((void**)&mpl,  g_mpl);

    cudaFuncSetAttribute(gemm_mma<0>,  cudaFuncAttributeMaxDynamicSharedMemorySize, GSMEM);
    cudaFuncSetAttribute(gemm_mma<3>,  cudaFuncAttributeMaxDynamicSharedMemorySize, GSMEM);
    cudaFuncSetAttribute(gemm_mma<9>,  cudaFuncAttributeMaxDynamicSharedMemorySize, GSMEM);
    cudaFuncSetAttribute(gemm_mma<13>, cudaFuncAttributeMaxDynamicSharedMemorySize, GSMEM);

    // weight plane conversion (once per forward)
    auto conv = [](const float* s, __nv_bfloat16* h, __nv_bfloat16* l, size_t n) {
        int n4 = (int)(n >> 2);
        convert_planes<<<(n4 + 255) / 256, 256>>>(s, h, l, n4);
    };
    conv(wte,         wteh, wtel, (size_t)VV * CC);
    conv(attn_w,      awh,  awl,  (size_t)LL * C3 * CC);
    conv(attn_proj_w, aph,  apl,  (size_t)LL * CC * CC);
    conv(fc_w,        fch,  fcl,  (size_t)LL * C4 * CC);
    conv(mlp_proj_w,  mph,  mpl,  (size_t)LL * CC * C4);

    embed_kernel<<<(MM * CC + 255) / 256, 256>>>(idx, wte, wpe);

    for (int l = 0; l < LL; l++) {
        ln_kernel<<<MM, 256>>>(x, ln1_w + l * CC, ln1_b + l * CC, lnh, lnl);
        gemm_mma<9><<<dim3(MM / 128, C3 / 128), 256, GSMEM>>>(
            lnh, lnl, awh + (size_t)l * C3 * CC, awl + (size_t)l * C3 * CC,
            attn_b + l * C3, nullptr, nullptr, qkvh, qkvl, C3, CC);
        flash_attn<<<dim3(TT / 64, BB * HH), 128>>>(qkvh, qkvl, yh, yl);
        gemm_mma<3><<<dim3(MM / 128, CC / 128), 256, GSMEM>>>(
            yh, yl, aph + (size_t)l * CC * CC, apl + (size_t)l * CC * CC,
            attn_proj_b + l * CC, x, x, nullptr, nullptr, CC, CC);
        ln_kernel<<<MM, 256>>>(x, ln2_w + l * CC, ln2_b + l * CC, lnh, lnl);
        gemm_mma<13><<<dim3(MM / 128, C4 / 128), 256, GSMEM>>>(
            lnh, lnl, fch + (size_t)l * C4 * CC, fcl + (size_t)l * C4 * CC,
            fc_b + l * C4, nullptr, nullptr, mlph, mlpl, C4, CC);
        gemm_mma<3><<<dim3(MM / 128, CC / 128), 256, GSMEM>>>(
            mlph, mlpl, mph + (size_t)l * CC * C4, mpl + (size_t)l * CC * C4,
            mlp_proj_b + l * CC, x, x, nullptr, nullptr, CC, C4);
    }

    ln_kernel<<<MM, 256>>>(x, lnf_w, lnf_b, lnh, lnl);
    gemm_mma<0><<<dim3(MM / 128, VV / 128), 256, GSMEM>>>(
        lnh, lnl, wteh, wtel, nullptr, nullptr, out, nullptr, nullptr, VV, CC);
}

// round 6
// speedup vs baseline: 3.3504x; 1.0914x over previous
#include <cuda_runtime.h>
#include <cuda_bf16.h>
#include <math.h>
#include <cstdint>

#define BB 2
#define TT 1024
#define LL 12
#define HH 12
#define CC 768
#define VV 50304
#define HD 64
#define MM (BB*TT)    // 2048 rows
#define C3 (3*CC)     // 2304
#define C4 (4*CC)     // 3072

// ---------------- scratch (static device allocations; no cudaMalloc) ----------
__device__ float g_x[MM*CC];                         // residual stream (fp32)
__device__ __nv_bfloat16 g_lnh[MM*CC],  g_lnl[MM*CC];
__device__ __nv_bfloat16 g_qkvh[MM*C3], g_qkvl[MM*C3];
__device__ __nv_bfloat16 g_yh[MM*CC],   g_yl[MM*CC];
__device__ __nv_bfloat16 g_mlph[MM*C4], g_mlpl[MM*C4];
__device__ __nv_bfloat16 g_wteh[(size_t)VV*CC], g_wtel[(size_t)VV*CC];
__device__ __nv_bfloat16 g_awh[(size_t)LL*C3*CC], g_awl[(size_t)LL*C3*CC];
__device__ __nv_bfloat16 g_aph[(size_t)LL*CC*CC], g_apl[(size_t)LL*CC*CC];
__device__ __nv_bfloat16 g_fch[(size_t)LL*C4*CC], g_fcl[(size_t)LL*C4*CC];
__device__ __nv_bfloat16 g_mph[(size_t)LL*CC*C4], g_mpl[(size_t)LL*CC*C4];

// =================== common helpers ============================================
__device__ __forceinline__ uint32_t smem_u32(const void* p) {
    uint32_t a;
    asm("{ .reg .u64 t; cvta.to.shared.u64 t, %1; cvt.u32.u64 %0, t; }"
        : "=r"(a) : "l"(p));
    return a;
}

#define MMA16816(d, A0,A1,A2,A3, B0,B1) \
    asm volatile("mma.sync.aligned.m16n8k16.row.col.f32.bf16.bf16.f32 " \
        "{%0,%1,%2,%3}, {%4,%5,%6,%7}, {%8,%9}, {%0,%1,%2,%3};" \
        : "+f"((d)[0]), "+f"((d)[1]), "+f"((d)[2]), "+f"((d)[3]) \
        : "r"(A0), "r"(A1), "r"(A2), "r"(A3), "r"(B0), "r"(B1))

#define LDSM_X4(r0,r1,r2,r3, a) \
    asm volatile("ldmatrix.sync.aligned.m8n8.x4.shared.b16 {%0,%1,%2,%3}, [%4];" \
        : "=r"(r0), "=r"(r1), "=r"(r2), "=r"(r3) : "r"(a))
#define LDSM_X4_T(r0,r1,r2,r3, a) \
    asm volatile("ldmatrix.sync.aligned.m8n8.x4.trans.shared.b16 {%0,%1,%2,%3}, [%4];" \
        : "=r"(r0), "=r"(r1), "=r"(r2), "=r"(r3) : "r"(a))

#define CP_ASYNC16(saddr, gptr) \
    asm volatile("cp.async.cg.shared.global [%0], [%1], 16;" \
        :: "r"(saddr), "l"(gptr) : "memory")
#define CP_COMMIT() asm volatile("cp.async.commit_group;" ::: "memory")
#define CP_WAIT(n)  asm volatile("cp.async.wait_group %0;" :: "n"(n) : "memory")

__device__ __forceinline__ uint32_t pack_bf2(float x, float y) {
    __nv_bfloat162 h = __floats2bfloat162_rn(x, y);
    return reinterpret_cast<uint32_t&>(h);
}
__device__ __forceinline__ void split_bf(float v, __nv_bfloat16& h, __nv_bfloat16& l) {
    h = __float2bfloat16_rn(v);
    l = __float2bfloat16_rn(v - __bfloat162float(h));
}

// ---------------- fp32 -> bf16 hi/lo plane conversion --------------------------
__global__ void convert_planes(const float* __restrict__ src,
                               __nv_bfloat16* __restrict__ hi,
                               __nv_bfloat16* __restrict__ lo, int n4) {
    int i = blockIdx.x * blockDim.x + threadIdx.x;
    if (i >= n4) return;
    float4 f = ((const float4*)src)[i];
    float hx = __bfloat162float(__float2bfloat16_rn(f.x));
    float hy = __bfloat162float(__float2bfloat16_rn(f.y));
    float hz = __bfloat162float(__float2bfloat16_rn(f.z));
    float hw = __bfloat162float(__float2bfloat16_rn(f.w));
    ((uint2*)hi)[i] = make_uint2(pack_bf2(f.x, f.y), pack_bf2(f.z, f.w));
    ((uint2*)lo)[i] = make_uint2(pack_bf2(f.x - hx, f.y - hy),
                                 pack_bf2(f.z - hz, f.w - hw));
}

// =================== bf16x3 HMMA GEMM on pre-split planes ======================
// C = A * B^T. CTA 128x128, 8 warps (4M x 2N), BK=32, cp.async 2-stage,
// ldmatrix fragment loads. EPI: 1=+bias 2=+resid(fp32) 4=gelu 8=emit planes
#define PITCHB 80
#define MATB   (128 * PITCHB)
#define STAGEB (4 * MATB)         // Ah|Al|Bh|Bl
#define GSMEM  (2 * STAGEB)       // 81920 B

__device__ __forceinline__ void issue_cp(uint32_t dst0,
    const __nv_bfloat16* a0, const __nv_bfloat16* a1,
    const __nv_bfloat16* b0, const __nv_bfloat16* b1,
    int K, int k0, int tid)
{
    const __nv_bfloat16* gs[4] = {a0, a1, b0, b1};
    int r_lo = tid >> 2, c16 = tid & 3;
#pragma unroll
    for (int i = 0; i < 8; i++) {
        int p = i >> 1;
        int r = (i & 1) * 64 + r_lo;
        const __nv_bfloat16* g = gs[p] + (size_t)r * K + k0 + c16 * 8;
        CP_ASYNC16(dst0 + p * MATB + r * PITCHB + c16 * 16, g);
    }
}

template<int EPI>
__global__ __launch_bounds__(256, 2) void gemm_mma(
    const __nv_bfloat16* __restrict__ Ah, const __nv_bfloat16* __restrict__ Al,
    const __nv_bfloat16* __restrict__ Bh, const __nv_bfloat16* __restrict__ Bl,
    const float* __restrict__ bias, const float* __restrict__ resid,
    float* __restrict__ Cf, __nv_bfloat16* __restrict__ Ch,
    __nv_bfloat16* __restrict__ Cl, int N, int K)
{
    extern __shared__ __align__(1024) char dyn[];
    const int tid  = threadIdx.x;
    const int wid  = tid >> 5;
    const int lane = tid & 31;
    const int g    = lane >> 2;
    const int tg   = lane & 3;
    const int wm   = wid & 3;
    const int wn   = wid >> 2;
    const int bm = blockIdx.x, bn = blockIdx.y;

    const int lrow = lane & 7, lsel = lane >> 3;
    const uint32_t a_off = (uint32_t)((((lsel & 1) * 8 + lrow) * PITCHB) + (lsel >> 1) * 16);
    const uint32_t b_off = (uint32_t)((((lsel >> 1) * 8 + lrow) * PITCHB) + (lsel & 1) * 16);

    const __nv_bfloat16* A0 = Ah + (size_t)bm * 128 * K;
    const __nv_bfloat16* A1 = Al + (size_t)bm * 128 * K;
    const __nv_bfloat16* B0 = Bh + (size_t)bn * 128 * K;
    const __nv_bfloat16* B1 = Bl + (size_t)bn * 128 * K;
    const int nch = K >> 5;
    const uint32_t sm0 = smem_u32(dyn);

    float acc[2][8][4];
#pragma unroll
    for (int mi = 0; mi < 2; mi++)
#pragma unroll
        for (int j = 0; j < 8; j++)
#pragma unroll
            for (int q = 0; q < 4; q++) acc[mi][j][q] = 0.f;

    issue_cp(sm0, A0, A1, B0, B1, K, 0, tid);
    CP_COMMIT();

    for (int c = 0; c < nch; c++) {
        const int s = c & 1;
        if (c + 1 < nch) {
            issue_cp(sm0 + ((c + 1) & 1) * STAGEB, A0, A1, B0, B1,
                     K, (c + 1) << 5, tid);
            CP_COMMIT();
            CP_WAIT(1);
        } else {
            CP_WAIT(0);
        }
        __syncthreads();

        const uint32_t sA  = sm0 + s * STAGEB;
        const uint32_t sAl = sA + MATB;
        const uint32_t sB  = sA + 2 * MATB;
        const uint32_t sBl = sA + 3 * MATB;
        const uint32_t arow = (wm * 32) * PITCHB;
        const uint32_t brow = (wn * 64) * PITCHB;

#pragma unroll
        for (int kk = 0; kk < 2; kk++) {
            const uint32_t kb = kk * 32;
            uint32_t a[2][4], al[2][4], b[8][2];
#pragma unroll
            for (int mi = 0; mi < 2; mi++)
                LDSM_X4(a[mi][0], a[mi][1], a[mi][2], a[mi][3],
                        sA + arow + mi * (16 * PITCHB) + kb + a_off);
#pragma unroll
            for (int j = 0; j < 8; j += 2)
                LDSM_X4(b[j][0], b[j][1], b[j+1][0], b[j+1][1],
                        sB + brow + j * (8 * PITCHB) + kb + b_off);
#pragma unroll
            for (int mi = 0; mi < 2; mi++)
#pragma unroll
                for (int j = 0; j < 8; j++)
                    MMA16816(acc[mi][j], a[mi][0], a[mi][1], a[mi][2], a[mi][3],
                             b[j][0], b[j][1]);
#pragma unroll
            for (int mi = 0; mi < 2; mi++)
                LDSM_X4(al[mi][0], al[mi][1], al[mi][2], al[mi][3],
                        sAl + arow + mi * (16 * PITCHB) + kb + a_off);
#pragma unroll
            for (int mi = 0; mi < 2; mi++)
#pragma unroll
                for (int j = 0; j < 8; j++)
                    MMA16816(acc[mi][j], al[mi][0], al[mi][1], al[mi][2], al[mi][3],
                             b[j][0], b[j][1]);
#pragma unroll
            for (int j = 0; j < 8; j += 2)
                LDSM_X4(b[j][0], b[j][1], b[j+1][0], b[j+1][1],
                        sBl + brow + j * (8 * PITCHB) + kb + b_off);
#pragma unroll
            for (int mi = 0; mi < 2; mi++)
#pragma unroll
                for (int j = 0; j < 8; j++)
                    MMA16816(acc[mi][j], a[mi][0], a[mi][1], a[mi][2], a[mi][3],
                             b[j][0], b[j][1]);
        }
        __syncthreads();
    }

    // ---- epilogue ----
#pragma unroll
    for (int mi = 0; mi < 2; mi++) {
#pragma unroll
        for (int j = 0; j < 8; j++) {
            int r0  = bm * 128 + wm * 32 + mi * 16 + g;
            int col = bn * 128 + wn * 64 + j * 8 + tg * 2;
            float v00 = acc[mi][j][0], v01 = acc[mi][j][1];
            float v10 = acc[mi][j][2], v11 = acc[mi][j][3];
            if (EPI & 1) {
                float bx = bias[col], by = bias[col + 1];
                v00 += bx; v01 += by; v10 += bx; v11 += by;
            }
            if (EPI & 4) {
                v00 = 0.5f * v00 * (1.0f + erff(v00 * 0.70710678118654752f));
                v01 = 0.5f * v01 * (1.0f + erff(v01 * 0.70710678118654752f));
                v10 = 0.5f * v10 * (1.0f + erff(v10 * 0.70710678118654752f));
                v11 = 0.5f * v11 * (1.0f + erff(v11 * 0.70710678118654752f));
            }
            size_t o0 = (size_t)r0 * N + col;
            size_t o1 = (size_t)(r0 + 8) * N + col;
            if (EPI & 8) {
                float h00 = __bfloat162float(__float2bfloat16_rn(v00));
                float h01 = __bfloat162float(__float2bfloat16_rn(v01));
                float h10 = __bfloat162float(__float2bfloat16_rn(v10));
                float h11 = __bfloat162float(__float2bfloat16_rn(v11));
                *(uint32_t*)(Ch + o0) = pack_bf2(v00, v01);
                *(uint32_t*)(Ch + o1) = pack_bf2(v10, v11);
                *(uint32_t*)(Cl + o0) = pack_bf2(v00 - h00, v01 - h01);
                *(uint32_t*)(Cl + o1) = pack_bf2(v10 - h10, v11 - h11);
            } else {
                if (EPI & 2) {
                    float2 r00 = *(const float2*)(resid + o0);
                    float2 r11 = *(const float2*)(resid + o1);
                    v00 += r00.x; v01 += r00.y; v10 += r11.x; v11 += r11.y;
                }
                *(float2*)(Cf + o0) = make_float2(v00, v01);
                *(float2*)(Cf + o1) = make_float2(v10, v11);
            }
        }
    }
}

// ---------------- embedding ---------------------------------------------------
__global__ void embed_kernel(const int* __restrict__ idx,
                             const float* __restrict__ wte,
                             const float* __restrict__ wpe) {
    int i = blockIdx.x * blockDim.x + threadIdx.x;
    if (i >= MM * CC) return;
    int row = i / CC, c = i - row * CC;
    int t = row & (TT - 1);
    int tok = idx[row];
    g_x[i] = wte[(size_t)tok * CC + c] + wpe[(size_t)t * CC + c];
}

// ---------------- layernorm: fp32 in -> bf16 hi/lo planes out ------------------
__global__ __launch_bounds__(256) void ln_kernel(const float* __restrict__ in,
                                                 const float* __restrict__ w,
                                                 const float* __restrict__ b,
                                                 __nv_bfloat16* __restrict__ oh,
                                                 __nv_bfloat16* __restrict__ ol) {
    int row = blockIdx.x;
    const float* x = in + (size_t)row * CC;
    int t = threadIdx.x;
    float v[3];
    float s = 0.f, s2 = 0.f;
#pragma unroll
    for (int i = 0; i < 3; i++) {
        float u = x[t + i * 256];
        v[i] = u; s += u; s2 += u * u;
    }
    __shared__ float sh[16];
#pragma unroll
    for (int o = 16; o > 0; o >>= 1) {
        s  += __shfl_down_sync(0xffffffffu, s,  o);
        s2 += __shfl_down_sync(0xffffffffu, s2, o);
    }
    int lane = t & 31, wid = t >> 5;
    if (lane == 0) { sh[wid] = s; sh[8 + wid] = s2; }
    __syncthreads();
    if (wid == 0) {
        s  = (lane < 8) ? sh[lane]     : 0.f;
        s2 = (lane < 8) ? sh[8 + lane] : 0.f;
#pragma unroll
        for (int o = 4; o > 0; o >>= 1) {
            s  += __shfl_down_sync(0xffffffffu, s,  o);
            s2 += __shfl_down_sync(0xffffffffu, s2, o);
        }
        if (lane == 0) { sh[0] = s; sh[8] = s2; }
    }
    __syncthreads();
    float mean = sh[0] * (1.0f / CC);
    float var  = sh[8] * (1.0f / CC) - mean * mean;
    float rstd = rsqrtf(var + 1e-5f);
#pragma unroll
    for (int i = 0; i < 3; i++) {
        int c = t + i * 256;
        float val = (v[i] - mean) * rstd * w[c] + b[c];
        __nv_bfloat16 h, l;
        split_bf(val, h, l);
        oh[(size_t)row * CC + c] = h;
        ol[(size_t)row * CC + c] = l;
    }
}

// =================== fused flash attention (bf16x3 HMMA, ldmatrix) =============
#define KPB 144   // 72 bf16 pitch in bytes
__global__ __launch_bounds__(128) void flash_attn(
    const __nv_bfloat16* __restrict__ qh, const __nv_bfloat16* __restrict__ ql,
    __nv_bfloat16* __restrict__ yh, __nv_bfloat16* __restrict__ yl)
{
    const int qt = (gridDim.x - 1) - blockIdx.x;     // heavy tiles first
    const int bh = blockIdx.y;
    const int b = bh / HH, h = bh - b * HH;
    const int tid = threadIdx.x, wq = tid >> 5, lane = tid & 31;
    const int g = lane >> 2, tg = lane & 3;
    const int lrow = lane & 7, lsel = lane >> 3;

    __shared__ __nv_bfloat16 Kh[64][72], Kl[64][72];   // [key][d]
    __shared__ __nv_bfloat16 Vh[64][72], Vl[64][72];   // [key][d] (natural)
    const uint32_t khb = smem_u32(&Kh[0][0]);
    const uint32_t klb = smem_u32(&Kl[0][0]);
    const uint32_t vhb = smem_u32(&Vh[0][0]);
    const uint32_t vlb = smem_u32(&Vl[0][0]);
    // ldmatrix per-lane offsets:
    const uint32_t koff = (uint32_t)((((lsel >> 1) * 8 + lrow) * KPB) + (lsel & 1) * 16);
    const uint32_t voff = (uint32_t)((((lsel & 1) * 8 + lrow) * KPB) + (lsel >> 1) * 16);

    // Q fragments held across k-tiles
    uint32_t Qh[4][4], Ql[4][4];
    {
        const __nv_bfloat16* qbh = qh + ((size_t)(b * TT + qt * 64 + wq * 16)) * C3 + h * HD;
        const __nv_bfloat16* qbl = ql + ((size_t)(b * TT + qt * 64 + wq * 16)) * C3 + h * HD;
#pragma unroll
        for (int kk = 0; kk < 4; kk++) {
            int c0 = kk * 16 + tg * 2;
            Qh[kk][0] = *(const uint32_t*)(qbh + (size_t)g * C3 + c0);
            Qh[kk][1] = *(const uint32_t*)(qbh + (size_t)(g + 8) * C3 + c0);
            Qh[kk][2] = *(const uint32_t*)(qbh + (size_t)g * C3 + c0 + 8);
            Qh[kk][3] = *(const uint32_t*)(qbh + (size_t)(g + 8) * C3 + c0 + 8);
            Ql[kk][0] = *(const uint32_t*)(qbl + (size_t)g * C3 + c0);
            Ql[kk][1] = *(const uint32_t*)(qbl + (size_t)(g + 8) * C3 + c0);
            Ql[kk][2] = *(const uint32_t*)(qbl + (size_t)g * C3 + c0 + 8);
            Ql[kk][3] = *(const uint32_t*)(qbl + (size_t)(g + 8) * C3 + c0 + 8);
        }
    }

    float m0 = -1e30f, m1 = -1e30f, l0 = 0.f, l1 = 0.f;
    float O[8][4];
#pragma unroll
    for (int j = 0; j < 8; j++)
#pragma unroll
        for (int q = 0; q < 4; q++) O[j][q] = 0.f;

    for (int kt = 0; kt <= qt; kt++) {
        __syncthreads();
        // stage K and V tiles [key][d], vectorized
#pragma unroll
        for (int i = 0; i < 4; i++) {
            int e = tid + i * 128;
            int r = e >> 3, c16 = e & 7;
            size_t gk = ((size_t)(b * TT + kt * 64 + r)) * C3 + CC + h * HD + c16 * 8;
            size_t gv = gk + CC;
            *(uint4*)&Kh[r][c16 * 8] = *(const uint4*)(qh + gk);
            *(uint4*)&Kl[r][c16 * 8] = *(const uint4*)(ql + gk);
            *(uint4*)&Vh[r][c16 * 8] = *(const uint4*)(qh + gv);
            *(uint4*)&Vl[r][c16 * 8] = *(const uint4*)(ql + gv);
        }
        __syncthreads();

        // S = Q K^T (bf16x3)
        float S[8][4];
#pragma unroll
        for (int j = 0; j < 8; j++)
#pragma unroll
            for (int q = 0; q < 4; q++) S[j][q] = 0.f;
#pragma unroll
        for (int kk = 0; kk < 4; kk++) {
            uint32_t bK[8][2], cK[8][2];
#pragma unroll
            for (int j = 0; j < 8; j += 2) {
                LDSM_X4(bK[j][0], bK[j][1], bK[j+1][0], bK[j+1][1],
                        khb + j * (8 * KPB) + kk * 32 + koff);
                LDSM_X4(cK[j][0], cK[j][1], cK[j+1][0], cK[j+1][1],
                        klb + j * (8 * KPB) + kk * 32 + koff);
            }
#pragma unroll
            for (int j = 0; j < 8; j++) {
                MMA16816(S[j], Qh[kk][0], Qh[kk][1], Qh[kk][2], Qh[kk][3], bK[j][0], bK[j][1]);
                MMA16816(S[j], Ql[kk][0], Ql[kk][1], Ql[kk][2], Ql[kk][3], bK[j][0], bK[j][1]);
                MMA16816(S[j], Qh[kk][0], Qh[kk][1], Qh[kk][2], Qh[kk][3], cK[j][0], cK[j][1]);
            }
        }

        // scale + causal mask
        const int row0 = wq * 16 + g, row1 = row0 + 8;
#pragma unroll
        for (int j = 0; j < 8; j++) {
            int cl = j * 8 + tg * 2;
            S[j][0] *= 0.125f; S[j][1] *= 0.125f;
            S[j][2] *= 0.125f; S[j][3] *= 0.125f;
            if (kt == qt) {
                if (cl     > row0) S[j][0] = -1e30f;
                if (cl + 1 > row0) S[j][1] = -1e30f;
                if (cl     > row1) S[j][2] = -1e30f;
                if (cl + 1 > row1) S[j][3] = -1e30f;
            }
        }
        float mn0 = m0, mn1 = m1;
#pragma unroll
        for (int j = 0; j < 8; j++) {
            mn0 = fmaxf(mn0, fmaxf(S[j][0], S[j][1]));
            mn1 = fmaxf(mn1, fmaxf(S[j][2], S[j][3]));
        }
        mn0 = fmaxf(mn0, __shfl_xor_sync(0xffffffffu, mn0, 1));
        mn0 = fmaxf(mn0, __shfl_xor_sync(0xffffffffu, mn0, 2));
        mn1 = fmaxf(mn1, __shfl_xor_sync(0xffffffffu, mn1, 1));
        mn1 = fmaxf(mn1, __shfl_xor_sync(0xffffffffu, mn1, 2));
        float sc0 = __expf(m0 - mn0), sc1 = __expf(m1 - mn1);
        m0 = mn0; m1 = mn1;

        uint32_t PH0[8], PH1[8], PL0[8], PL1[8];
        float rs0 = 0.f, rs1 = 0.f;
#pragma unroll
        for (int j = 0; j < 8; j++) {
            float p0 = __expf(S[j][0] - mn0), p1 = __expf(S[j][1] - mn0);
            float p2 = __expf(S[j][2] - mn1), p3 = __expf(S[j][3] - mn1);
            rs0 += p0 + p1; rs1 += p2 + p3;
            float h0 = __bfloat162float(__float2bfloat16_rn(p0));
            float h1 = __bfloat162float(__float2bfloat16_rn(p1));
            float h2 = __bfloat162float(__float2bfloat16_rn(p2));
            float h3 = __bfloat162float(__float2bfloat16_rn(p3));
            PH0[j] = pack_bf2(p0, p1);  PH1[j] = pack_bf2(p2, p3);
            PL0[j] = pack_bf2(p0 - h0, p1 - h1);
            PL1[j] = pack_bf2(p2 - h2, p3 - h3);
        }
        rs0 += __shfl_xor_sync(0xffffffffu, rs0, 1);
        rs0 += __shfl_xor_sync(0xffffffffu, rs0, 2);
        rs1 += __shfl_xor_sync(0xffffffffu, rs1, 1);
        rs1 += __shfl_xor_sync(0xffffffffu, rs1, 2);
        l0 = l0 * sc0 + rs0;
        l1 = l1 * sc1 + rs1;

#pragma unroll
        for (int j = 0; j < 8; j++) {
            O[j][0] *= sc0; O[j][1] *= sc0;
            O[j][2] *= sc1; O[j][3] *= sc1;
        }
        // O += P V via ldmatrix.trans on natural V layout
#pragma unroll
        for (int t = 0; t < 4; t++) {
            uint32_t ah0 = PH0[2*t], ah1 = PH1[2*t], ah2 = PH0[2*t+1], ah3 = PH1[2*t+1];
            uint32_t al0 = PL0[2*t], al1 = PL1[2*t], al2 = PL0[2*t+1], al3 = PL1[2*t+1];
            uint32_t bV[8][2], cV[8][2];
#pragma unroll
            for (int jd = 0; jd < 8; jd += 2) {
                LDSM_X4_T(bV[jd][0], bV[jd][1], bV[jd+1][0], bV[jd+1][1],
                          vhb + t * (16 * KPB) + jd * 16 + voff);
                LDSM_X4_T(cV[jd][0], cV[jd][1], cV[jd+1][0], cV[jd+1][1],
                          vlb + t * (16 * KPB) + jd * 16 + voff);
            }
#pragma unroll
            for (int jd = 0; jd < 8; jd++) {
                MMA16816(O[jd], ah0, ah1, ah2, ah3, bV[jd][0], bV[jd][1]);
                MMA16816(O[jd], al0, al1, al2, al3, bV[jd][0], bV[jd][1]);
                MMA16816(O[jd], ah0, ah1, ah2, ah3, cV[jd][0], cV[jd][1]);
            }
        }
    }

    // finalize and store y planes
    float inv0 = 1.0f / l0, inv1 = 1.0f / l1;
    int t0 = qt * 64 + wq * 16 + g;
    size_t base0 = ((size_t)(b * TT) + t0) * CC + h * HD;
    size_t base1 = base0 + (size_t)8 * CC;
#pragma unroll
    for (int jd = 0; jd < 8; jd++) {
        int d = jd * 8 + tg * 2;
        float v0 = O[jd][0] * inv0, v1 = O[jd][1] * inv0;
        float v2 = O[jd][2] * inv1, v3 = O[jd][3] * inv1;
        float h0 = __bfloat162float(__float2bfloat16_rn(v0));
        float h1 = __bfloat162float(__float2bfloat16_rn(v1));
        float h2 = __bfloat162float(__float2bfloat16_rn(v2));
        float h3 = __bfloat162float(__float2bfloat16_rn(v3));
        *(uint32_t*)(yh + base0 + d) = pack_bf2(v0, v1);
        *(uint32_t*)(yh + base1 + d) = pack_bf2(v2, v3);
        *(uint32_t*)(yl + base0 + d) = pack_bf2(v0 - h0, v1 - h1);
        *(uint32_t*)(yl + base1 + d) = pack_bf2(v2 - h2, v3 - h3);
    }
}

// ---------------- host orchestration ------------------------------------------
extern "C" void kernel_launch(void* const* d_in, const int* in_sizes, int n_in,
                              void* d_out, int out_size) {
    (void)in_sizes; (void)n_in; (void)out_size;
    const int*   idx          = (const int*)  d_in[0];
    const float* wte          = (const float*)d_in[1];
    const float* wpe          = (const float*)d_in[2];
    const float* ln1_w        = (const float*)d_in[3];
    const float* ln1_b        = (const float*)d_in[4];
    const float* attn_w       = (const float*)d_in[5];
    const float* attn_b       = (const float*)d_in[6];
    const float* attn_proj_w  = (const float*)d_in[7];
    const float* attn_proj_b  = (const float*)d_in[8];
    const float* ln2_w        = (const float*)d_in[9];
    const float* ln2_b        = (const float*)d_in[10];
    const float* fc_w         = (const float*)d_in[11];
    const float* fc_b         = (const float*)d_in[12];
    const float* mlp_proj_w   = (const float*)d_in[13];
    const float* mlp_proj_b   = (const float*)d_in[14];
    const float* lnf_w        = (const float*)d_in[15];
    const float* lnf_b        = (const float*)d_in[16];
    float* out = (float*)d_out;

    float* x;
    __nv_bfloat16 *lnh, *lnl, *qkvh, *qkvl, *yh, *yl, *mlph, *mlpl;
    __nv_bfloat16 *wteh, *wtel, *awh, *awl, *aph, *apl, *fch, *fcl, *mph, *mpl;
    cudaGetSymbolAddress((void**)&x,    g_x);
    cudaGetSymbolAddress((void**)&lnh,  g_lnh);   cudaGetSymbolAddress((void**)&lnl,  g_lnl);
    cudaGetSymbolAddress((void**)&qkvh, g_qkvh);  cudaGetSymbolAddress((void**)&qkvl, g_qkvl);
    cudaGetSymbolAddress((void**)&yh,   g_yh);    cudaGetSymbolAddress((void**)&yl,   g_yl);
    cudaGetSymbolAddress((void**)&mlph, g_mlph);  cudaGetSymbolAddress((void**)&mlpl, g_mlpl);
    cudaGetSymbolAddress((void**)&wteh, g_wteh);  cudaGetSymbolAddress((void**)&wtel, g_wtel);
    cudaGetSymbolAddress((void**)&awh,  g_awh);   cudaGetSymbolAddress((void**)&awl,  g_awl);
    cudaGetSymbolAddress((void**)&aph,  g_aph);   cudaGetSymbolAddress((void**)&apl,  g_apl);
    cudaGetSymbolAddress((void**)&fch,  g_fch);   cudaGetSymbolAddress((void**)&fcl,  g_fcl);
    cudaGetSymbolAddress((void**)&mph,  g_mph);   cudaGetSymbolAddress((void**)&mpl,  g_mpl);

    cudaFuncSetAttribute(gemm_mma<0>,  cudaFuncAttributeMaxDynamicSharedMemorySize, GSMEM);
    cudaFuncSetAttribute(gemm_mma<3>,  cudaFuncAttributeMaxDynamicSharedMemorySize, GSMEM);
    cudaFuncSetAttribute(gemm_mma<9>,  cudaFuncAttributeMaxDynamicSharedMemorySize, GSMEM);
    cudaFuncSetAttribute(gemm_mma<13>, cudaFuncAttributeMaxDynamicSharedMemorySize, GSMEM);

    auto conv = [](const float* s, __nv_bfloat16* h, __nv_bfloat16* l, size_t n) {
        int n4 = (int)(n >> 2);
        convert_planes<<<(n4 + 255) / 256, 256>>>(s, h, l, n4);
    };

    // Launch order arranged so ncu (-s 5 -c 1) captures the qkv GEMM.
    conv(attn_w, awh, awl, (size_t)LL * C3 * CC);                       // 0
    embed_kernel<<<(MM * CC + 255) / 256, 256>>>(idx, wte, wpe);        // 1
    ln_kernel<<<MM, 256>>>(x, ln1_w, ln1_b, lnh, lnl);                  // 2
    conv(wte,         wteh, wtel, (size_t)VV * CC);                     // 3
    conv(attn_proj_w, aph,  apl,  (size_t)LL * CC * CC);                // 4
    gemm_mma<9><<<dim3(MM / 128, C3 / 128), 256, GSMEM>>>(              // 5 (profiled)
        lnh, lnl, awh, awl, attn_b, nullptr, nullptr, qkvh, qkvl, C3, CC);
    conv(fc_w,        fch,  fcl,  (size_t)LL * C4 * CC);                // 6
    conv(mlp_proj_w,  mph,  mpl,  (size_t)LL * CC * C4);                // 7

    for (int l = 0; l < LL; l++) {
        if (l > 0) {
            ln_kernel<<<MM, 256>>>(x, ln1_w + l * CC, ln1_b + l * CC, lnh, lnl);
            gemm_mma<9><<<dim3(MM / 128, C3 / 128), 256, GSMEM>>>(
                lnh, lnl, awh + (size_t)l * C3 * CC, awl + (size_t)l * C3 * CC,
                attn_b + l * C3, nullptr, nullptr, qkvh, qkvl, C3, CC);
        }
        flash_attn<<<dim3(TT / 64, BB * HH), 128>>>(qkvh, qkvl, yh, yl);
        gemm_mma<3><<<dim3(MM / 128, CC / 128), 256, GSMEM>>>(
            yh, yl, aph + (size_t)l * CC * CC, apl + (size_t)l * CC * CC,
            attn_proj_b + l * CC, x, x, nullptr, nullptr, CC, CC);
        ln_kernel<<<MM, 256>>>(x, ln2_w + l * CC, ln2_b + l * CC, lnh, lnl);
        gemm_mma<13><<<dim3(MM / 128, C4 / 128), 256, GSMEM>>>(
            lnh, lnl, fch + (size_t)l * C4 * CC, fcl + (size_t)l * C4 * CC,
            fc_b + l * C4, nullptr, nullptr, mlph, mlpl, C4, CC);
        gemm_mma<3><<<dim3(MM / 128, CC / 128), 256, GSMEM>>>(
            mlph, mlpl, mph + (size_t)l * CC * C4, mpl + (size_t)l * CC * C4,
            mlp_proj_b + l * CC, x, x, nullptr, nullptr, CC, C4);
    }

    ln_kernel<<<MM, 256>>>(x, lnf_w, lnf_b, lnh, lnl);
    gemm_mma<0><<<dim3(MM / 128, VV / 128), 256, GSMEM>>>(
        lnh, lnl, wteh, wtel, nullptr, nullptr, out, nullptr, nullptr, VV, CC);
}